// round 1
// baseline (speedup 1.0000x reference)
#include <cuda_runtime.h>
#include <cstdint>
#include <cstddef>

// ---------------------------------------------------------------------------
// Problem constants
// ---------------------------------------------------------------------------
#define BATCH 8
#define CH    512
#define CQD   64           // C/8
#define HW    4096         // 64*64
#define MTOT  832          // 64+64+512+64+64+64 packed projection rows

// scratch layout (in floats)
#define OFF_W    0u                         // 425984  packed weights [832,512]
#define OFF_BI   425984u                    // 1024    packed bias
#define OFF_Y    427008u                    // 8*832*4096 = 27262976 projections
#define OFF_E    27689984u                  // 8*4096*4096 = 134217728 energy/attn
#define OFF_CE   161907712u                 // 8*64*64 = 32768 channel energy
#define OFF_CEP  161940480u                 // 16*8*4096 = 524288 partials
#define OFF_CO   162464768u                 // 8*64*4096 = 2097152 channel out
#define SCRATCH_FLOATS 164561920u

__device__ float g_scratch[SCRATCH_FLOATS];

// ---------------------------------------------------------------------------
// f32x2 packed-math helpers (sm_103a FFMA2 path)
// ---------------------------------------------------------------------------
__device__ __forceinline__ unsigned long long pk2(float lo, float hi) {
    unsigned long long r;
    asm("mov.b64 %0, {%1, %2};" : "=l"(r) : "f"(lo), "f"(hi));
    return r;
}
__device__ __forceinline__ unsigned long long fma2(unsigned long long a,
                                                   unsigned long long b,
                                                   unsigned long long c) {
    unsigned long long d;
    asm("fma.rn.f32x2 %0, %1, %2, %3;" : "=l"(d) : "l"(a), "l"(b), "l"(c));
    return d;
}
__device__ __forceinline__ float2 u2f(unsigned long long u) {
    float2 f;
    asm("mov.b64 {%0, %1}, %2;" : "=f"(f.x), "=f"(f.y) : "l"(u));
    return f;
}

// ---------------------------------------------------------------------------
// Generic batched SIMT GEMM:  C[b] = A[b] @ B[b] (+ bias[m]) (+= existing C)
//   TRANS_A=false: A is [M,K] row-major (lda = row stride)
//   TRANS_A=true : A memory is [K,M] row-major (lda = row stride over m-dim),
//                  i.e. logical A[m][k] = Amem[k*lda + m]
// Tile 128x128x16, 256 threads, 8x8 per thread, FFMA2 inner product.
// ---------------------------------------------------------------------------
#define BM 128
#define BN 128
#define BKK 16

template<bool TRANS_A, bool ACCUM, bool HAS_BIAS>
__global__ __launch_bounds__(256, 2)
void gemm_f32(const float* __restrict__ A, const float* __restrict__ Bm,
              const float* __restrict__ bias, float* __restrict__ Cm,
              int M, int N, int K, int lda, int ldb, int ldc,
              size_t sA, size_t sB, size_t sC)
{
    __shared__ float As[BKK][BM + 4];
    __shared__ float Bs[BKK][BN];

    const int b  = blockIdx.z;
    const float* Ab = A + (size_t)b * sA;
    const float* Bb = Bm + (size_t)b * sB;
    float*       Cb = Cm + (size_t)b * sC;

    const int m0 = blockIdx.y * BM;
    const int n0 = blockIdx.x * BN;
    const int t  = threadIdx.x;
    const int tm0 = (t >> 4) << 3;   // 0..120
    const int tn0 = (t & 15) << 3;   // 0..120

    unsigned long long acc[8][4];
#pragma unroll
    for (int i = 0; i < 8; i++)
#pragma unroll
        for (int j = 0; j < 4; j++) acc[i][j] = 0ull;

    for (int k0 = 0; k0 < K; k0 += BKK) {
        // ---- load A tile into As[k][m] ----
        if (TRANS_A) {
#pragma unroll
            for (int r = 0; r < 2; r++) {
                int idx = t + r * 256;           // 0..511
                int kr  = idx >> 5;              // 0..15
                int m4  = (idx & 31) << 2;       // 0..124
                float4 v = make_float4(0.f, 0.f, 0.f, 0.f);
                if (m0 + m4 < M)
                    v = *reinterpret_cast<const float4*>(
                        Ab + (size_t)(k0 + kr) * lda + m0 + m4);
                *reinterpret_cast<float4*>(&As[kr][m4]) = v;
            }
        } else {
#pragma unroll
            for (int r = 0; r < 2; r++) {
                int idx = t + r * 256;
                int row = idx >> 2;              // 0..127
                int c4  = (idx & 3) << 2;        // 0,4,8,12
                float4 v = make_float4(0.f, 0.f, 0.f, 0.f);
                if (m0 + row < M)
                    v = *reinterpret_cast<const float4*>(
                        Ab + (size_t)(m0 + row) * lda + k0 + c4);
                As[c4 + 0][row] = v.x;
                As[c4 + 1][row] = v.y;
                As[c4 + 2][row] = v.z;
                As[c4 + 3][row] = v.w;
            }
        }
        // ---- load B tile into Bs[k][n] ----
#pragma unroll
        for (int r = 0; r < 2; r++) {
            int idx = t + r * 256;
            int kr  = idx >> 5;
            int n4  = (idx & 31) << 2;
            float4 v = *reinterpret_cast<const float4*>(
                Bb + (size_t)(k0 + kr) * ldb + n0 + n4);
            *reinterpret_cast<float4*>(&Bs[kr][n4]) = v;
        }
        __syncthreads();

#pragma unroll
        for (int kk = 0; kk < BKK; kk++) {
            float4 a0 = *reinterpret_cast<const float4*>(&As[kk][tm0]);
            float4 a1 = *reinterpret_cast<const float4*>(&As[kk][tm0 + 4]);
            ulonglong2 bl0 = *reinterpret_cast<const ulonglong2*>(&Bs[kk][tn0]);
            ulonglong2 bl1 = *reinterpret_cast<const ulonglong2*>(&Bs[kk][tn0 + 4]);
            unsigned long long bv[4] = {bl0.x, bl0.y, bl1.x, bl1.y};
            float av[8] = {a0.x, a0.y, a0.z, a0.w, a1.x, a1.y, a1.z, a1.w};
#pragma unroll
            for (int i = 0; i < 8; i++) {
                unsigned long long a2 = pk2(av[i], av[i]);
#pragma unroll
                for (int j = 0; j < 4; j++)
                    acc[i][j] = fma2(a2, bv[j], acc[i][j]);
            }
        }
        __syncthreads();
    }

    // ---- epilogue ----
#pragma unroll
    for (int i = 0; i < 8; i++) {
        int m = m0 + tm0 + i;
        if (m >= M) continue;
        float bsv = 0.0f;
        if (HAS_BIAS) bsv = bias[m];
        float* crow = Cb + (size_t)m * ldc + n0 + tn0;
#pragma unroll
        for (int j = 0; j < 4; j++) {
            float2 f = u2f(acc[i][j]);
            f.x += bsv; f.y += bsv;
            if (ACCUM) {
                float2 o = *reinterpret_cast<const float2*>(crow + j * 2);
                f.x += o.x; f.y += o.y;
            }
            *reinterpret_cast<float2*>(crow + j * 2) = f;
        }
    }
}

// ---------------------------------------------------------------------------
// Row softmax in place over E rows of length 4096 (one block per row)
// ---------------------------------------------------------------------------
__global__ void row_softmax(float* __restrict__ E)
{
    __shared__ float red[256];
    const size_t row = blockIdx.x;
    float* rp = E + row * (size_t)HW;
    const int t = threadIdx.x;

    float v[16];
    float m = -1e30f;
#pragma unroll
    for (int i = 0; i < 16; i++) {
        v[i] = rp[t + i * 256];
        m = fmaxf(m, v[i]);
    }
    red[t] = m; __syncthreads();
    for (int s = 128; s > 0; s >>= 1) {
        if (t < s) red[t] = fmaxf(red[t], red[t + s]);
        __syncthreads();
    }
    m = red[0]; __syncthreads();

    float s = 0.f;
#pragma unroll
    for (int i = 0; i < 16; i++) {
        v[i] = __expf(v[i] - m);
        s += v[i];
    }
    red[t] = s; __syncthreads();
    for (int s2 = 128; s2 > 0; s2 >>= 1) {
        if (t < s2) red[t] += red[t + s2];
        __syncthreads();
    }
    float inv = 1.0f / red[0];
#pragma unroll
    for (int i = 0; i < 16; i++) rp[t + i * 256] = v[i] * inv;
}

// ---------------------------------------------------------------------------
// Channel energy partials: part[split][b][p][q] = sum_{n in split} cq[p,n]*ck[q,n]
// grid (16 splits, B), 256 threads, 4x4 outputs per thread
// ---------------------------------------------------------------------------
__global__ void chan_energy(const float* __restrict__ cq, const float* __restrict__ ck,
                            float* __restrict__ part)
{
    __shared__ float sq[64][65];
    __shared__ float sk[64][65];
    const int b = blockIdx.y;
    const int split = blockIdx.x;
    const float* cqb = cq + (size_t)b * MTOT * HW;
    const float* ckb = ck + (size_t)b * MTOT * HW;
    const int t = threadIdx.x;
    const int p0 = (t >> 4) * 4;
    const int q0 = (t & 15) * 4;

    float acc[4][4];
#pragma unroll
    for (int i = 0; i < 4; i++)
#pragma unroll
        for (int j = 0; j < 4; j++) acc[i][j] = 0.f;

    for (int c = 0; c < 4; c++) {
        const int nb = (split * 4 + c) * 64;
        __syncthreads();
#pragma unroll
        for (int i = 0; i < 16; i++) {
            int idx = t + i * 256;
            int row = idx >> 6, col = idx & 63;
            sq[row][col] = cqb[(size_t)row * HW + nb + col];
            sk[row][col] = ckb[(size_t)row * HW + nb + col];
        }
        __syncthreads();
        for (int nn = 0; nn < 64; nn++) {
            float aq[4], bk[4];
#pragma unroll
            for (int i = 0; i < 4; i++) aq[i] = sq[p0 + i][nn];
#pragma unroll
            for (int j = 0; j < 4; j++) bk[j] = sk[q0 + j][nn];
#pragma unroll
            for (int i = 0; i < 4; i++)
#pragma unroll
                for (int j = 0; j < 4; j++)
                    acc[i][j] += aq[i] * bk[j];
        }
    }
    float* out = part + (size_t)split * (BATCH * 4096) + (size_t)b * 4096;
#pragma unroll
    for (int i = 0; i < 4; i++)
#pragma unroll
        for (int j = 0; j < 4; j++)
            out[(p0 + i) * 64 + (q0 + j)] = acc[i][j];
}

__global__ void reduce_ce(const float* __restrict__ part, float* __restrict__ cE)
{
    int i = blockIdx.x * 256 + threadIdx.x;   // 0..32767
    float s = 0.f;
#pragma unroll
    for (int k = 0; k < 16; k++) s += part[(size_t)k * (BATCH * 4096) + i];
    cE[i] = s;
}

// ---------------------------------------------------------------------------
// Channel softmax: rows of 64, one block (64 threads) per row
// ---------------------------------------------------------------------------
__global__ void chan_softmax(float* __restrict__ cE)
{
    __shared__ float red[64];
    const int row = blockIdx.x;        // 0..B*64-1
    float* rp = cE + (size_t)row * 64;
    const int t = threadIdx.x;         // 64 threads
    float v = rp[t];
    red[t] = v; __syncthreads();
    for (int s = 32; s > 0; s >>= 1) {
        if (t < s) red[t] = fmaxf(red[t], red[t + s]);
        __syncthreads();
    }
    float m = red[0]; __syncthreads();
    float e = __expf(v - m);
    red[t] = e; __syncthreads();
    for (int s = 32; s > 0; s >>= 1) {
        if (t < s) red[t] += red[t + s];
        __syncthreads();
    }
    rp[t] = e / red[0];
}

// ---------------------------------------------------------------------------
// Channel output: c_out[b][p][n] = sum_q attn[b][p][q] * cv[b][q][n]
// grid (16, B), 256 threads, each thread owns one n column, 64 p accumulators
// ---------------------------------------------------------------------------
__global__ void chan_out(const float* __restrict__ cattn, const float* __restrict__ cv,
                         float* __restrict__ cout)
{
    __shared__ float sa[4096];
    const int b = blockIdx.y;
    const int n = blockIdx.x * 256 + threadIdx.x;
    const float* at = cattn + (size_t)b * 4096;
    for (int i = threadIdx.x; i < 4096; i += 256) sa[i] = at[i];
    __syncthreads();

    const float* cvb = cv + (size_t)b * MTOT * HW;
    float acc[64];
#pragma unroll
    for (int p = 0; p < 64; p++) acc[p] = 0.f;
    for (int q = 0; q < 64; q++) {
        float vv = cvb[(size_t)q * HW + n];
#pragma unroll
        for (int p = 0; p < 64; p++) acc[p] += sa[p * 64 + q] * vv;
    }
    float* ob = cout + (size_t)b * CQD * HW;
#pragma unroll
    for (int p = 0; p < 64; p++) ob[(size_t)p * HW + n] = acc[p];
}

// ---------------------------------------------------------------------------
// Launch
// ---------------------------------------------------------------------------
extern "C" void kernel_launch(void* const* d_in, const int* in_sizes, int n_in,
                              void* d_out, int out_size)
{
    (void)in_sizes; (void)n_in; (void)out_size;

    const float* x = (const float*)d_in[0];

    float* S = nullptr;
    cudaGetSymbolAddress((void**)&S, g_scratch);

    float* W   = S + OFF_W;
    float* BI  = S + OFF_BI;
    float* Y   = S + OFF_Y;
    float* E   = S + OFF_E;
    float* CE  = S + OFF_CE;
    float* CEP = S + OFF_CEP;
    float* CO  = S + OFF_CO;
    float* out = (float*)d_out;

    // pack weights: rows [0:64)=pq, [64:128)=pk, [128:640)=pv, [640:704)=cq,
    //               [704:768)=ck, [768:832)=cv
    cudaMemcpyAsync(W +      0, d_in[1],  64  * 512 * sizeof(float), cudaMemcpyDeviceToDevice);
    cudaMemcpyAsync(W +  32768, d_in[3],  64  * 512 * sizeof(float), cudaMemcpyDeviceToDevice);
    cudaMemcpyAsync(W +  65536, d_in[5],  512 * 512 * sizeof(float), cudaMemcpyDeviceToDevice);
    cudaMemcpyAsync(W + 327680, d_in[7],  64  * 512 * sizeof(float), cudaMemcpyDeviceToDevice);
    cudaMemcpyAsync(W + 360448, d_in[9],  64  * 512 * sizeof(float), cudaMemcpyDeviceToDevice);
    cudaMemcpyAsync(W + 393216, d_in[11], 64  * 512 * sizeof(float), cudaMemcpyDeviceToDevice);
    cudaMemcpyAsync(BI +   0, d_in[2],  64  * sizeof(float), cudaMemcpyDeviceToDevice);
    cudaMemcpyAsync(BI +  64, d_in[4],  64  * sizeof(float), cudaMemcpyDeviceToDevice);
    cudaMemcpyAsync(BI + 128, d_in[6],  512 * sizeof(float), cudaMemcpyDeviceToDevice);
    cudaMemcpyAsync(BI + 640, d_in[8],  64  * sizeof(float), cudaMemcpyDeviceToDevice);
    cudaMemcpyAsync(BI + 704, d_in[10], 64  * sizeof(float), cudaMemcpyDeviceToDevice);
    cudaMemcpyAsync(BI + 768, d_in[12], 64  * sizeof(float), cudaMemcpyDeviceToDevice);

    dim3 blk(256);

    // K1: all projections  Y[b] = W @ x[b] + bias   (M=832,N=4096,K=512)
    gemm_f32<false, false, true><<<dim3(32, 7, BATCH), blk>>>(
        W, x, BI, Y, MTOT, HW, CH, CH, HW, HW,
        (size_t)0, (size_t)CH * HW, (size_t)MTOT * HW);

    // K2: energy  E[b] = q^T @ k   (M=N=4096,K=64), q rows at Y+0, k rows at Y+64*HW
    gemm_f32<true, false, false><<<dim3(32, 32, BATCH), blk>>>(
        Y, Y + (size_t)64 * HW, nullptr, E, HW, HW, CQD, HW, HW, HW,
        (size_t)MTOT * HW, (size_t)MTOT * HW, (size_t)HW * HW);

    // K3: softmax rows of E in place -> P
    row_softmax<<<BATCH * HW, 256>>>(E);

    // K4: pos_out = v @ P  -> d_out   (M=512,N=4096,K=4096), v rows at Y+128*HW
    gemm_f32<false, false, false><<<dim3(32, 4, BATCH), blk>>>(
        Y + (size_t)128 * HW, E, nullptr, out, CH, HW, HW, HW, HW, HW,
        (size_t)MTOT * HW, (size_t)HW * HW, (size_t)CH * HW);

    // Channel path (cq at Y+640*HW, ck at Y+704*HW, cv at Y+768*HW)
    chan_energy<<<dim3(16, BATCH), 256>>>(Y + (size_t)640 * HW, Y + (size_t)704 * HW, CEP);
    reduce_ce<<<128, 256>>>(CEP, CE);
    chan_softmax<<<BATCH * 64, 64>>>(CE);
    chan_out<<<dim3(16, BATCH), 256>>>(CE, Y + (size_t)768 * HW, CO);

    // K8: d_out += co_w @ c_out + co_b   (M=512,N=4096,K=64)
    gemm_f32<false, true, true><<<dim3(32, 4, BATCH), blk>>>(
        (const float*)d_in[13], CO, (const float*)d_in[14], out,
        CH, HW, CQD, CQD, HW, HW,
        (size_t)0, (size_t)CQD * HW, (size_t)CH * HW);
}

// round 3
// speedup vs baseline: 2.0473x; 2.0473x over previous
#include <cuda_runtime.h>
#include <cuda_bf16.h>
#include <cstdint>
#include <cstddef>

// ---------------------------------------------------------------------------
// Problem constants
// ---------------------------------------------------------------------------
#define BATCH 8
#define CH    512
#define CQD   64
#define HW    4096
#define MTOT  832          // packed projection rows (pq,pk,pv,cq,ck,cv)
#define MPAD  896          // padded to multiple of 128

// scratch layout (float offsets)
#define OFF_W    0u            // packed fp32 weights [832,512]
#define OFF_BI   425984u       // packed bias
#define OFF_WH   427008u       // Whi bf16 [896,512]
#define OFF_WL   656384u
#define OFF_XH   885760u       // xhi bf16 [8,512,4096]
#define OFF_XL   9274368u
#define OFF_Y    17662976u     // fp32 projections [8,896,4096]
#define OFF_QTH  47023104u     // qT hi bf16 [8,4096,64]
#define OFF_QTL  48071680u
#define OFF_KH   49120256u     // k hi bf16 [8,64,4096]
#define OFF_KL   50168832u
#define OFF_VH   51217408u     // v hi bf16 [8,512,4096]
#define OFF_VL   59606016u
#define OFF_E    67994624u     // fp32 energy [8,4096,4096]
#define OFF_PH   202212352u    // P hi bf16 [8,4096,4096]
#define OFF_PL   269321216u
#define OFF_CE   336430080u
#define OFF_CEP  336462848u
#define OFF_CO   336987136u
#define SCRATCH_FLOATS 339084288u

__device__ float g_scratch[SCRATCH_FLOATS];

// ---------------------------------------------------------------------------
// PTX helpers (base-ISA only: mma.sync / ldmatrix / cp.async)
// ---------------------------------------------------------------------------
__device__ __forceinline__ uint32_t smem_to_u32(const void* p) {
    uint32_t a;
    asm("{ .reg .u64 t; cvta.to.shared.u64 t, %1; cvt.u32.u64 %0, t; }" : "=r"(a) : "l"(p));
    return a;
}

__device__ __forceinline__ void ldsm4(uint32_t* r, uint32_t addr) {
    asm volatile("ldmatrix.sync.aligned.m8n8.x4.shared.b16 {%0,%1,%2,%3}, [%4];"
                 : "=r"(r[0]), "=r"(r[1]), "=r"(r[2]), "=r"(r[3]) : "r"(addr));
}
__device__ __forceinline__ void ldsm4t(uint32_t* r, uint32_t addr) {
    asm volatile("ldmatrix.sync.aligned.m8n8.x4.trans.shared.b16 {%0,%1,%2,%3}, [%4];"
                 : "=r"(r[0]), "=r"(r[1]), "=r"(r[2]), "=r"(r[3]) : "r"(addr));
}
__device__ __forceinline__ void mma16816(float* c, const uint32_t* a,
                                         uint32_t b0, uint32_t b1) {
    asm volatile("mma.sync.aligned.m16n8k16.row.col.f32.bf16.bf16.f32 "
                 "{%0,%1,%2,%3}, {%4,%5,%6,%7}, {%8,%9}, {%0,%1,%2,%3};"
                 : "+f"(c[0]), "+f"(c[1]), "+f"(c[2]), "+f"(c[3])
                 : "r"(a[0]), "r"(a[1]), "r"(a[2]), "r"(a[3]), "r"(b0), "r"(b1));
}
__device__ __forceinline__ void cp16(uint32_t dst, const void* src) {
    asm volatile("cp.async.cg.shared.global [%0], [%1], 16;" :: "r"(dst), "l"(src));
}
#define CP_COMMIT() asm volatile("cp.async.commit_group;" ::: "memory")
#define CP_WAIT1()  asm volatile("cp.async.wait_group 1;"  ::: "memory")

// ---------------------------------------------------------------------------
// bf16-split GEMM via mma.sync (HMMA):
//   C[b][M,N](fp32) = (Ah+Al)[b] @ (Bh+Bl)[b]   using hh + hl + lh terms
// A: [M,K] row-major bf16.  B: [K,N] row-major bf16.  M,N multiples of 128,
// K multiple of 32.
// CTA tile 128x128, BK=32, 3 cp.async stages, 8 warps (4m x 2n), warp 32x64.
// ---------------------------------------------------------------------------
#define STAGES  3
#define APITCH  40                      // bf16 elems per A smem row (80B)
#define BPITCH  136                     // bf16 elems per B smem row (272B)
#define A_STG   (128 * APITCH * 2)      // 10240 B per hi/lo buffer
#define B_STG   (32 * BPITCH * 2)       // 8704 B
#define STG_BYTES (2 * A_STG + 2 * B_STG)   // 37888
#define GSMEM_BYTES (STAGES * STG_BYTES)    // 113664

__global__ void __launch_bounds__(256, 1) gemm_mma(
    const __nv_bfloat16* __restrict__ Ah, const __nv_bfloat16* __restrict__ Al,
    const __nv_bfloat16* __restrict__ Bh, const __nv_bfloat16* __restrict__ Bl,
    const float* __restrict__ bias, float* __restrict__ C,
    int K, int lda, int ldb, int ldc,
    size_t sA, size_t sB, size_t sC, int has_bias)
{
    extern __shared__ char smem[];
    const uint32_t sb = smem_to_u32(smem);
    const int tid  = threadIdx.x;
    const int w    = tid >> 5, lane = tid & 31;
    const int wm   = w & 3,    wn   = w >> 2;
    const int b    = blockIdx.z;
    const int m0   = blockIdx.y * 128, n0 = blockIdx.x * 128;

    const __nv_bfloat16* Ag[2] = { Ah + (size_t)b * sA + (size_t)m0 * lda,
                                   Al + (size_t)b * sA + (size_t)m0 * lda };
    const __nv_bfloat16* Bg[2] = { Bh + (size_t)b * sB + n0,
                                   Bl + (size_t)b * sB + n0 };

    const int nk = K >> 5;

    // per-thread copy coordinates
    const int a_row = tid >> 2, a_ch = (tid & 3) << 3;     // 64 rows / iter
    const int b_row = tid >> 4, b_ch = (tid & 15) << 3;    // 16 rows / iter

    // ---- async copy of chunk kt into stage buffer ----
    auto issue = [&](int stage, int kt) {
        const uint32_t base = sb + stage * STG_BYTES;
        const int k0 = kt << 5;
#pragma unroll
        for (int h = 0; h < 2; h++) {
            const __nv_bfloat16* asrc = Ag[h] + k0;
            const uint32_t adst = base + h * A_STG;
#pragma unroll
            for (int r = 0; r < 2; r++) {
                int row = a_row + r * 64;
                cp16(adst + (uint32_t)(row * APITCH + a_ch) * 2,
                     asrc + (size_t)row * lda + a_ch);
            }
            const __nv_bfloat16* bsrc = Bg[h];
            const uint32_t bdst = base + 2 * A_STG + h * B_STG;
#pragma unroll
            for (int r = 0; r < 2; r++) {
                int row = b_row + r * 16;
                cp16(bdst + (uint32_t)(row * BPITCH + b_ch) * 2,
                     bsrc + (size_t)(k0 + row) * ldb + b_ch);
            }
        }
    };

    float c[2][8][4];
#pragma unroll
    for (int mi = 0; mi < 2; mi++)
#pragma unroll
        for (int j = 0; j < 8; j++)
#pragma unroll
            for (int q = 0; q < 4; q++) c[mi][j][q] = 0.0f;

    // prologue: 2 stages in flight
    issue(0, 0); CP_COMMIT();
    if (nk > 1) issue(1, 1);
    CP_COMMIT();

    const uint32_t a_lane_off = (uint32_t)((lane & 15) * APITCH + ((lane >> 4) << 3)) * 2;
    const uint32_t b_lane_off = (uint32_t)((lane & 15) * BPITCH + ((lane >> 4) << 3)) * 2;

    for (int kt = 0; kt < nk; kt++) {
        CP_WAIT1();
        __syncthreads();
        int kf = kt + STAGES - 1;
        if (kf < nk) issue(kf % STAGES, kf);
        CP_COMMIT();

        const int stage = kt % STAGES;
        const uint32_t ab = sb + stage * STG_BYTES;
        const uint32_t bb = ab + 2 * A_STG;

#pragma unroll
        for (int ks = 0; ks < 2; ks++) {
            uint32_t afr[2][2][4];     // [h][mi][4]
            uint32_t bfr[2][4][4];     // [h][nj][4]
#pragma unroll
            for (int h = 0; h < 2; h++) {
#pragma unroll
                for (int mi = 0; mi < 2; mi++)
                    ldsm4(afr[h][mi],
                          ab + h * A_STG + a_lane_off +
                          (uint32_t)((wm * 32 + mi * 16) * APITCH + ks * 16) * 2);
#pragma unroll
                for (int nj = 0; nj < 4; nj++)
                    ldsm4t(bfr[h][nj],
                           bb + h * B_STG + b_lane_off +
                           (uint32_t)(ks * 16 * BPITCH + wn * 64 + nj * 16) * 2);
            }
#pragma unroll
            for (int mi = 0; mi < 2; mi++)
#pragma unroll
                for (int j = 0; j < 8; j++) {
                    const int nj = j >> 1, hf = (j & 1) << 1;
                    mma16816(c[mi][j], afr[0][mi], bfr[0][nj][hf], bfr[0][nj][hf + 1]);
                    mma16816(c[mi][j], afr[0][mi], bfr[1][nj][hf], bfr[1][nj][hf + 1]);
                    mma16816(c[mi][j], afr[1][mi], bfr[0][nj][hf], bfr[0][nj][hf + 1]);
                }
        }
        __syncthreads();
    }

    // ---- epilogue ----
#pragma unroll
    for (int mi = 0; mi < 2; mi++) {
        const int r0 = m0 + wm * 32 + mi * 16 + (lane >> 2);
        const float bv0 = has_bias ? bias[r0]     : 0.0f;
        const float bv1 = has_bias ? bias[r0 + 8] : 0.0f;
        float* p0 = C + (size_t)b * sC + (size_t)r0 * ldc + n0 + wn * 64 + (lane & 3) * 2;
        float* p1 = p0 + (size_t)8 * ldc;
#pragma unroll
        for (int j = 0; j < 8; j++) {
            float2 v0 = make_float2(c[mi][j][0] + bv0, c[mi][j][1] + bv0);
            float2 v1 = make_float2(c[mi][j][2] + bv1, c[mi][j][3] + bv1);
            *reinterpret_cast<float2*>(p0 + j * 8) = v0;
            *reinterpret_cast<float2*>(p1 + j * 8) = v1;
        }
    }
}

// ---------------------------------------------------------------------------
// bf16 split conversions
// ---------------------------------------------------------------------------
__global__ void split4(const float* __restrict__ in, __nv_bfloat16* __restrict__ hi,
                       __nv_bfloat16* __restrict__ lo, int count4,
                       size_t in_bs, size_t out_bs)
{
    size_t b = blockIdx.y;
    int i = blockIdx.x * 256 + threadIdx.x;
    if (i >= count4) return;
    float4 v = reinterpret_cast<const float4*>(in + b * in_bs)[i];
    __nv_bfloat16 h0 = __float2bfloat16(v.x), h1 = __float2bfloat16(v.y);
    __nv_bfloat16 h2 = __float2bfloat16(v.z), h3 = __float2bfloat16(v.w);
    __nv_bfloat16 l0 = __float2bfloat16(v.x - __bfloat162float(h0));
    __nv_bfloat16 l1 = __float2bfloat16(v.y - __bfloat162float(h1));
    __nv_bfloat16 l2 = __float2bfloat16(v.z - __bfloat162float(h2));
    __nv_bfloat16 l3 = __float2bfloat16(v.w - __bfloat162float(h3));
    __nv_bfloat162* ph = reinterpret_cast<__nv_bfloat162*>(hi + b * out_bs);
    __nv_bfloat162* pl = reinterpret_cast<__nv_bfloat162*>(lo + b * out_bs);
    ph[2 * i]     = __nv_bfloat162(h0, h1);
    ph[2 * i + 1] = __nv_bfloat162(h2, h3);
    pl[2 * i]     = __nv_bfloat162(l0, l1);
    pl[2 * i + 1] = __nv_bfloat162(l2, l3);
}

__global__ void splitW(const float* __restrict__ in, __nv_bfloat16* __restrict__ hi,
                       __nv_bfloat16* __restrict__ lo)
{
    int i = blockIdx.x * 256 + threadIdx.x;     // 0..896*512-1
    float v = (i < MTOT * CH) ? in[i] : 0.0f;
    __nv_bfloat16 h = __float2bfloat16(v);
    hi[i] = h;
    lo[i] = __float2bfloat16(v - __bfloat162float(h));
}

// q [64,HW] per batch (rows 0..63 of Y) -> qT [HW,64] hi/lo
__global__ void qtrans_split(const float* __restrict__ Y, __nv_bfloat16* __restrict__ qh,
                             __nv_bfloat16* __restrict__ ql)
{
    __shared__ float s[64][65];
    int b = blockIdx.y;
    int i0 = blockIdx.x * 64;
    const float* q = Y + (size_t)b * MPAD * HW;
    for (int u = threadIdx.x; u < 64 * 64; u += 256) {
        int c = u >> 6, i = u & 63;
        s[c][i] = q[(size_t)c * HW + i0 + i];
    }
    __syncthreads();
    for (int u = threadIdx.x; u < 64 * 64; u += 256) {
        int i = u >> 6, c = u & 63;
        float v = s[c][i];
        __nv_bfloat16 h = __float2bfloat16(v);
        size_t o = ((size_t)b * HW + i0 + i) * 64 + c;
        qh[o] = h;
        ql[o] = __float2bfloat16(v - __bfloat162float(h));
    }
}

// ---------------------------------------------------------------------------
// Row softmax over E rows of 4096, emits P as bf16 hi/lo
// ---------------------------------------------------------------------------
__global__ void softmax_p(const float* __restrict__ E, __nv_bfloat16* __restrict__ PH,
                          __nv_bfloat16* __restrict__ PL)
{
    __shared__ float red[256];
    const size_t row = blockIdx.x;
    const float* rp = E + row * (size_t)HW;
    const int t = threadIdx.x;

    float v[16];
    float m = -1e30f;
#pragma unroll
    for (int i = 0; i < 16; i++) {
        v[i] = rp[t + i * 256];
        m = fmaxf(m, v[i]);
    }
    red[t] = m; __syncthreads();
    for (int s = 128; s > 0; s >>= 1) {
        if (t < s) red[t] = fmaxf(red[t], red[t + s]);
        __syncthreads();
    }
    m = red[0]; __syncthreads();

    float s = 0.f;
#pragma unroll
    for (int i = 0; i < 16; i++) { v[i] = __expf(v[i] - m); s += v[i]; }
    red[t] = s; __syncthreads();
    for (int s2 = 128; s2 > 0; s2 >>= 1) {
        if (t < s2) red[t] += red[t + s2];
        __syncthreads();
    }
    float inv = 1.0f / red[0];
    __nv_bfloat16* ph = PH + row * (size_t)HW;
    __nv_bfloat16* pl = PL + row * (size_t)HW;
#pragma unroll
    for (int i = 0; i < 16; i++) {
        float p = v[i] * inv;
        __nv_bfloat16 h = __float2bfloat16(p);
        ph[t + i * 256] = h;
        pl[t + i * 256] = __float2bfloat16(p - __bfloat162float(h));
    }
}

// ---------------------------------------------------------------------------
// SIMT f32x2 GEMM (small K8 accumulate)
// ---------------------------------------------------------------------------
__device__ __forceinline__ unsigned long long pk2(float lo, float hi) {
    unsigned long long r;
    asm("mov.b64 %0, {%1, %2};" : "=l"(r) : "f"(lo), "f"(hi));
    return r;
}
__device__ __forceinline__ unsigned long long fma2(unsigned long long a,
                                                   unsigned long long b,
                                                   unsigned long long c) {
    unsigned long long d;
    asm("fma.rn.f32x2 %0, %1, %2, %3;" : "=l"(d) : "l"(a), "l"(b), "l"(c));
    return d;
}
__device__ __forceinline__ float2 u2f(unsigned long long u) {
    float2 f;
    asm("mov.b64 {%0, %1}, %2;" : "=f"(f.x), "=f"(f.y) : "l"(u));
    return f;
}

__global__ __launch_bounds__(256, 2)
void gemm_acc(const float* __restrict__ A, const float* __restrict__ Bm,
              const float* __restrict__ bias, float* __restrict__ Cm,
              int M, int N, int K, int lda, int ldb, int ldc,
              size_t sA, size_t sB, size_t sC)
{
    __shared__ float As[16][128 + 4];
    __shared__ float Bs[16][128];

    const int b  = blockIdx.z;
    const float* Ab = A + (size_t)b * sA;
    const float* Bb = Bm + (size_t)b * sB;
    float*       Cb = Cm + (size_t)b * sC;

    const int m0 = blockIdx.y * 128;
    const int n0 = blockIdx.x * 128;
    const int t  = threadIdx.x;
    const int tm0 = (t >> 4) << 3;
    const int tn0 = (t & 15) << 3;

    unsigned long long acc[8][4];
#pragma unroll
    for (int i = 0; i < 8; i++)
#pragma unroll
        for (int j = 0; j < 4; j++) acc[i][j] = 0ull;

    for (int k0 = 0; k0 < K; k0 += 16) {
#pragma unroll
        for (int r = 0; r < 2; r++) {
            int idx = t + r * 256;
            int row = idx >> 2;
            int c4  = (idx & 3) << 2;
            float4 v = make_float4(0.f, 0.f, 0.f, 0.f);
            if (m0 + row < M)
                v = *reinterpret_cast<const float4*>(Ab + (size_t)(m0 + row) * lda + k0 + c4);
            As[c4 + 0][row] = v.x; As[c4 + 1][row] = v.y;
            As[c4 + 2][row] = v.z; As[c4 + 3][row] = v.w;
        }
#pragma unroll
        for (int r = 0; r < 2; r++) {
            int idx = t + r * 256;
            int kr  = idx >> 5;
            int n4  = (idx & 31) << 2;
            float4 v = *reinterpret_cast<const float4*>(Bb + (size_t)(k0 + kr) * ldb + n0 + n4);
            *reinterpret_cast<float4*>(&Bs[kr][n4]) = v;
        }
        __syncthreads();
#pragma unroll
        for (int kk = 0; kk < 16; kk++) {
            float4 a0 = *reinterpret_cast<const float4*>(&As[kk][tm0]);
            float4 a1 = *reinterpret_cast<const float4*>(&As[kk][tm0 + 4]);
            ulonglong2 bl0 = *reinterpret_cast<const ulonglong2*>(&Bs[kk][tn0]);
            ulonglong2 bl1 = *reinterpret_cast<const ulonglong2*>(&Bs[kk][tn0 + 4]);
            unsigned long long bv[4] = {bl0.x, bl0.y, bl1.x, bl1.y};
            float av[8] = {a0.x, a0.y, a0.z, a0.w, a1.x, a1.y, a1.z, a1.w};
#pragma unroll
            for (int i = 0; i < 8; i++) {
                unsigned long long a2 = pk2(av[i], av[i]);
#pragma unroll
                for (int j = 0; j < 4; j++) acc[i][j] = fma2(a2, bv[j], acc[i][j]);
            }
        }
        __syncthreads();
    }
#pragma unroll
    for (int i = 0; i < 8; i++) {
        int m = m0 + tm0 + i;
        if (m >= M) continue;
        float bsv = bias[m];
        float* crow = Cb + (size_t)m * ldc + n0 + tn0;
#pragma unroll
        for (int j = 0; j < 4; j++) {
            float2 f = u2f(acc[i][j]);
            float2 o = *reinterpret_cast<const float2*>(crow + j * 2);
            f.x += bsv + o.x; f.y += bsv + o.y;
            *reinterpret_cast<float2*>(crow + j * 2) = f;
        }
    }
}

// ---------------------------------------------------------------------------
// Channel attention kernels (fp32, small)
// ---------------------------------------------------------------------------
__global__ void chan_energy(const float* __restrict__ cq, const float* __restrict__ ck,
                            float* __restrict__ part)
{
    __shared__ float sq[64][65];
    __shared__ float sk[64][65];
    const int b = blockIdx.y;
    const int split = blockIdx.x;
    const float* cqb = cq + (size_t)b * MPAD * HW;
    const float* ckb = ck + (size_t)b * MPAD * HW;
    const int t = threadIdx.x;
    const int p0 = (t >> 4) * 4;
    const int q0 = (t & 15) * 4;

    float acc[4][4];
#pragma unroll
    for (int i = 0; i < 4; i++)
#pragma unroll
        for (int j = 0; j < 4; j++) acc[i][j] = 0.f;

    for (int c = 0; c < 4; c++) {
        const int nb = (split * 4 + c) * 64;
        __syncthreads();
#pragma unroll
        for (int i = 0; i < 16; i++) {
            int idx = t + i * 256;
            int row = idx >> 6, col = idx & 63;
            sq[row][col] = cqb[(size_t)row * HW + nb + col];
            sk[row][col] = ckb[(size_t)row * HW + nb + col];
        }
        __syncthreads();
        for (int nn = 0; nn < 64; nn++) {
            float aq[4], bk[4];
#pragma unroll
            for (int i = 0; i < 4; i++) aq[i] = sq[p0 + i][nn];
#pragma unroll
            for (int j = 0; j < 4; j++) bk[j] = sk[q0 + j][nn];
#pragma unroll
            for (int i = 0; i < 4; i++)
#pragma unroll
                for (int j = 0; j < 4; j++) acc[i][j] += aq[i] * bk[j];
        }
    }
    float* out = part + (size_t)split * (BATCH * 4096) + (size_t)b * 4096;
#pragma unroll
    for (int i = 0; i < 4; i++)
#pragma unroll
        for (int j = 0; j < 4; j++)
            out[(p0 + i) * 64 + (q0 + j)] = acc[i][j];
}

__global__ void reduce_ce(const float* __restrict__ part, float* __restrict__ cE)
{
    int i = blockIdx.x * 256 + threadIdx.x;
    float s = 0.f;
#pragma unroll
    for (int k = 0; k < 16; k++) s += part[(size_t)k * (BATCH * 4096) + i];
    cE[i] = s;
}

__global__ void chan_softmax(float* __restrict__ cE)
{
    __shared__ float red[64];
    const int row = blockIdx.x;
    float* rp = cE + (size_t)row * 64;
    const int t = threadIdx.x;
    float v = rp[t];
    red[t] = v; __syncthreads();
    for (int s = 32; s > 0; s >>= 1) {
        if (t < s) red[t] = fmaxf(red[t], red[t + s]);
        __syncthreads();
    }
    float m = red[0]; __syncthreads();
    float e = __expf(v - m);
    red[t] = e; __syncthreads();
    for (int s = 32; s > 0; s >>= 1) {
        if (t < s) red[t] += red[t + s];
        __syncthreads();
    }
    rp[t] = e / red[0];
}

__global__ void chan_out(const float* __restrict__ cattn, const float* __restrict__ cv,
                         float* __restrict__ cout)
{
    __shared__ float sa[4096];
    const int b = blockIdx.y;
    const int n = blockIdx.x * 256 + threadIdx.x;
    const float* at = cattn + (size_t)b * 4096;
    for (int i = threadIdx.x; i < 4096; i += 256) sa[i] = at[i];
    __syncthreads();

    const float* cvb = cv + (size_t)b * MPAD * HW;
    float acc[64];
#pragma unroll
    for (int p = 0; p < 64; p++) acc[p] = 0.f;
    for (int q = 0; q < 64; q++) {
        float vv = cvb[(size_t)q * HW + n];
#pragma unroll
        for (int p = 0; p < 64; p++) acc[p] += sa[p * 64 + q] * vv;
    }
    float* ob = cout + (size_t)b * CQD * HW;
#pragma unroll
    for (int p = 0; p < 64; p++) ob[(size_t)p * HW + n] = acc[p];
}

// ---------------------------------------------------------------------------
// Launch
// ---------------------------------------------------------------------------
extern "C" void kernel_launch(void* const* d_in, const int* in_sizes, int n_in,
                              void* d_out, int out_size)
{
    (void)in_sizes; (void)n_in; (void)out_size;

    const float* x = (const float*)d_in[0];

    float* S = nullptr;
    cudaGetSymbolAddress((void**)&S, g_scratch);

    float* W   = S + OFF_W;
    float* BI  = S + OFF_BI;
    float* Y   = S + OFF_Y;
    float* E   = S + OFF_E;
    float* CE  = S + OFF_CE;
    float* CEP = S + OFF_CEP;
    float* CO  = S + OFF_CO;
    float* out = (float*)d_out;

    __nv_bfloat16* WH  = (__nv_bfloat16*)(S + OFF_WH);
    __nv_bfloat16* WL  = (__nv_bfloat16*)(S + OFF_WL);
    __nv_bfloat16* XH  = (__nv_bfloat16*)(S + OFF_XH);
    __nv_bfloat16* XL  = (__nv_bfloat16*)(S + OFF_XL);
    __nv_bfloat16* QTH = (__nv_bfloat16*)(S + OFF_QTH);
    __nv_bfloat16* QTL = (__nv_bfloat16*)(S + OFF_QTL);
    __nv_bfloat16* KH  = (__nv_bfloat16*)(S + OFF_KH);
    __nv_bfloat16* KL  = (__nv_bfloat16*)(S + OFF_KL);
    __nv_bfloat16* VH  = (__nv_bfloat16*)(S + OFF_VH);
    __nv_bfloat16* VL  = (__nv_bfloat16*)(S + OFF_VL);
    __nv_bfloat16* PH  = (__nv_bfloat16*)(S + OFF_PH);
    __nv_bfloat16* PL  = (__nv_bfloat16*)(S + OFF_PL);

    // pack fp32 weights + bias
    cudaMemcpyAsync(W +      0, d_in[1],  64  * 512 * sizeof(float), cudaMemcpyDeviceToDevice);
    cudaMemcpyAsync(W +  32768, d_in[3],  64  * 512 * sizeof(float), cudaMemcpyDeviceToDevice);
    cudaMemcpyAsync(W +  65536, d_in[5],  512 * 512 * sizeof(float), cudaMemcpyDeviceToDevice);
    cudaMemcpyAsync(W + 327680, d_in[7],  64  * 512 * sizeof(float), cudaMemcpyDeviceToDevice);
    cudaMemcpyAsync(W + 360448, d_in[9],  64  * 512 * sizeof(float), cudaMemcpyDeviceToDevice);
    cudaMemcpyAsync(W + 393216, d_in[11], 64  * 512 * sizeof(float), cudaMemcpyDeviceToDevice);
    cudaMemcpyAsync(BI +   0, d_in[2],  64  * sizeof(float), cudaMemcpyDeviceToDevice);
    cudaMemcpyAsync(BI +  64, d_in[4],  64  * sizeof(float), cudaMemcpyDeviceToDevice);
    cudaMemcpyAsync(BI + 128, d_in[6],  512 * sizeof(float), cudaMemcpyDeviceToDevice);
    cudaMemcpyAsync(BI + 640, d_in[8],  64  * sizeof(float), cudaMemcpyDeviceToDevice);
    cudaMemcpyAsync(BI + 704, d_in[10], 64  * sizeof(float), cudaMemcpyDeviceToDevice);
    cudaMemcpyAsync(BI + 768, d_in[12], 64  * sizeof(float), cudaMemcpyDeviceToDevice);

    cudaFuncSetAttribute(gemm_mma, cudaFuncAttributeMaxDynamicSharedMemorySize, GSMEM_BYTES);

    // bf16 splits of W and x
    splitW<<<(MPAD * CH + 255) / 256, 256>>>(W, WH, WL);
    split4<<<dim3(2048, BATCH), 256>>>(x, XH, XL, 524288, (size_t)CH * HW, (size_t)CH * HW);

    // K1: projections  Y = W @ x + bias   M=896 N=4096 K=512
    gemm_mma<<<dim3(32, 7, BATCH), 256, GSMEM_BYTES>>>(
        WH, WL, XH, XL, BI, Y, 512, 512, HW, HW,
        (size_t)0, (size_t)CH * HW, (size_t)MPAD * HW, 1);

    // bf16 splits of q (transposed), k, v
    qtrans_split<<<dim3(64, BATCH), 256>>>(Y, QTH, QTL);
    split4<<<dim3(256, BATCH), 256>>>(Y + (size_t)64 * HW, KH, KL, 65536,
                                      (size_t)MPAD * HW, (size_t)64 * HW);
    split4<<<dim3(2048, BATCH), 256>>>(Y + (size_t)128 * HW, VH, VL, 524288,
                                       (size_t)MPAD * HW, (size_t)CH * HW);

    // K2: energy  E = qT @ k   M=4096 N=4096 K=64
    gemm_mma<<<dim3(32, 32, BATCH), 256, GSMEM_BYTES>>>(
        QTH, QTL, KH, KL, nullptr, E, 64, 64, HW, HW,
        (size_t)HW * 64, (size_t)64 * HW, (size_t)HW * HW, 0);

    // K3: softmax -> P (bf16 hi/lo)
    softmax_p<<<BATCH * HW, 256>>>(E, PH, PL);

    // K4: pos_out = v @ P   M=512 N=4096 K=4096
    gemm_mma<<<dim3(32, 4, BATCH), 256, GSMEM_BYTES>>>(
        VH, VL, PH, PL, nullptr, out, HW, HW, HW, HW,
        (size_t)CH * HW, (size_t)HW * HW, (size_t)CH * HW, 0);

    // Channel path (fp32, Y rows 640/704/768)
    chan_energy<<<dim3(16, BATCH), 256>>>(Y + (size_t)640 * HW, Y + (size_t)704 * HW, CEP);
    reduce_ce<<<128, 256>>>(CEP, CE);
    chan_softmax<<<BATCH * 64, 64>>>(CE);
    chan_out<<<dim3(16, BATCH), 256>>>(CE, Y + (size_t)768 * HW, CO);

    // K8: d_out += co_w @ c_out + co_b   M=512 N=4096 K=64 (SIMT)
    gemm_acc<<<dim3(32, 4, BATCH), 256>>>(
        (const float*)d_in[13], CO, (const float*)d_in[14], out,
        CH, HW, CQD, CQD, HW, HW,
        (size_t)0, (size_t)CQD * HW, (size_t)CH * HW);
}

// round 4
// speedup vs baseline: 2.6886x; 1.3132x over previous
#include <cuda_runtime.h>
#include <cuda_fp16.h>
#include <cstdint>
#include <cstddef>

// ---------------------------------------------------------------------------
// Problem constants
// ---------------------------------------------------------------------------
#define BATCH 8
#define CH    512
#define CQD   64
#define HW    4096
#define MTOT  832          // packed projection rows (pq,pk,pv,cq,ck,cv)
#define MPAD  896          // padded to multiple of 128

// scratch layout (float offsets)
#define OFF_W    0u            // packed fp32 weights [832,512]
#define OFF_BI   425984u       // packed bias
#define OFF_WH   427008u       // W hi fp16 [896,512]
#define OFF_WL   656384u
#define OFF_XH   885760u       // x hi fp16 [8,512,4096]
#define OFF_XL   9274368u
#define OFF_Y    17662976u     // fp32 projections [8,896,4096]
#define OFF_QTH  47023104u     // qT hi fp16 [8,4096,64]
#define OFF_QTL  48071680u
#define OFF_KH   49120256u     // k hi fp16 [8,64,4096]
#define OFF_KL   50168832u
#define OFF_VH   51217408u     // v hi fp16 [8,512,4096]
#define OFF_VL   59606016u
#define OFF_E    67994624u     // fp32 energy [8,4096,4096]
#define OFF_PH   202212352u    // P fp16 [8,4096,4096]
#define OFF_CE   269321216u
#define OFF_CEP  269353984u
#define OFF_CO   269878272u
#define SCRATCH_FLOATS 271975424u

__device__ float g_scratch[SCRATCH_FLOATS];

// ---------------------------------------------------------------------------
// PTX helpers (base-ISA only: mma.sync / ldmatrix / cp.async)
// ---------------------------------------------------------------------------
__device__ __forceinline__ uint32_t smem_to_u32(const void* p) {
    uint32_t a;
    asm("{ .reg .u64 t; cvta.to.shared.u64 t, %1; cvt.u32.u64 %0, t; }" : "=r"(a) : "l"(p));
    return a;
}

__device__ __forceinline__ void ldsm4(uint32_t* r, uint32_t addr) {
    asm volatile("ldmatrix.sync.aligned.m8n8.x4.shared.b16 {%0,%1,%2,%3}, [%4];"
                 : "=r"(r[0]), "=r"(r[1]), "=r"(r[2]), "=r"(r[3]) : "r"(addr));
}
__device__ __forceinline__ void ldsm4t(uint32_t* r, uint32_t addr) {
    asm volatile("ldmatrix.sync.aligned.m8n8.x4.trans.shared.b16 {%0,%1,%2,%3}, [%4];"
                 : "=r"(r[0]), "=r"(r[1]), "=r"(r[2]), "=r"(r[3]) : "r"(addr));
}
__device__ __forceinline__ void mma16816(float* c, const uint32_t* a,
                                         uint32_t b0, uint32_t b1) {
    asm volatile("mma.sync.aligned.m16n8k16.row.col.f32.f16.f16.f32 "
                 "{%0,%1,%2,%3}, {%4,%5,%6,%7}, {%8,%9}, {%0,%1,%2,%3};"
                 : "+f"(c[0]), "+f"(c[1]), "+f"(c[2]), "+f"(c[3])
                 : "r"(a[0]), "r"(a[1]), "r"(a[2]), "r"(a[3]), "r"(b0), "r"(b1));
}
__device__ __forceinline__ void cp16(uint32_t dst, const void* src) {
    asm volatile("cp.async.cg.shared.global [%0], [%1], 16;" :: "r"(dst), "l"(src));
}
#define CP_COMMIT() asm volatile("cp.async.commit_group;" ::: "memory")
#define CP_WAIT1()  asm volatile("cp.async.wait_group 1;"  ::: "memory")

// ---------------------------------------------------------------------------
// fp16-split GEMM via mma.sync (HMMA), templated on B term count:
//   BT=2:  C = Ah@Bh + Ah@Bl + Al@Bh   (both operands split, ~2^-22)
//   BT=1:  C = Ah@B  + Al@B            (A split, B single fp16)
// A: [M,K] row-major fp16. B: [K,N] row-major fp16. M,N mult of 128, K of 32.
// CTA tile 128x128, BK=32, 3 cp.async stages, 8 warps (4m x 2n).
// ---------------------------------------------------------------------------
#define STAGES  3
#define APITCH  40                      // fp16 elems per A smem row (80B)
#define BPITCH  136                     // fp16 elems per B smem row (272B)
#define A_STG   (128 * APITCH * 2)      // 10240 B per hi/lo buffer
#define B_STG   (32 * BPITCH * 2)       // 8704 B

template<int BT>
__global__ void __launch_bounds__(256, (BT == 1) ? 2 : 1) gemm_mma(
    const __half* __restrict__ Ah, const __half* __restrict__ Al,
    const __half* __restrict__ Bh, const __half* __restrict__ Bl,
    const float* __restrict__ bias, float* __restrict__ C,
    int K, int lda, int ldb, int ldc,
    size_t sA, size_t sB, size_t sC, int has_bias)
{
    constexpr int STG_BYTES = 2 * A_STG + BT * B_STG;
    extern __shared__ char smem[];
    const uint32_t sb = smem_to_u32(smem);
    const int tid  = threadIdx.x;
    const int w    = tid >> 5, lane = tid & 31;
    const int wm   = w & 3,    wn   = w >> 2;
    const int b    = blockIdx.z;
    const int m0   = blockIdx.y * 128, n0 = blockIdx.x * 128;

    const __half* Ag[2] = { Ah + (size_t)b * sA + (size_t)m0 * lda,
                            Al + (size_t)b * sA + (size_t)m0 * lda };
    const __half* Bg[2] = { Bh + (size_t)b * sB + n0,
                            (BT == 2) ? (Bl + (size_t)b * sB + n0) : nullptr };

    const int nk = K >> 5;

    const int a_row = tid >> 2, a_ch = (tid & 3) << 3;     // 64 rows / iter
    const int b_row = tid >> 4, b_ch = (tid & 15) << 3;    // 16 rows / iter

    auto issue = [&](int stage, int kt) {
        const uint32_t base = sb + stage * STG_BYTES;
        const int k0 = kt << 5;
#pragma unroll
        for (int h = 0; h < 2; h++) {
            const __half* asrc = Ag[h] + k0;
            const uint32_t adst = base + h * A_STG;
#pragma unroll
            for (int r = 0; r < 2; r++) {
                int row = a_row + r * 64;
                cp16(adst + (uint32_t)(row * APITCH + a_ch) * 2,
                     asrc + (size_t)row * lda + a_ch);
            }
        }
#pragma unroll
        for (int h = 0; h < BT; h++) {
            const __half* bsrc = Bg[h];
            const uint32_t bdst = base + 2 * A_STG + h * B_STG;
#pragma unroll
            for (int r = 0; r < 2; r++) {
                int row = b_row + r * 16;
                cp16(bdst + (uint32_t)(row * BPITCH + b_ch) * 2,
                     bsrc + (size_t)(k0 + row) * ldb + b_ch);
            }
        }
    };

    float c[2][8][4];
#pragma unroll
    for (int mi = 0; mi < 2; mi++)
#pragma unroll
        for (int j = 0; j < 8; j++)
#pragma unroll
            for (int q = 0; q < 4; q++) c[mi][j][q] = 0.0f;

    issue(0, 0); CP_COMMIT();
    if (nk > 1) issue(1, 1);
    CP_COMMIT();

    const uint32_t a_lane_off = (uint32_t)((lane & 15) * APITCH + ((lane >> 4) << 3)) * 2;
    const uint32_t b_lane_off = (uint32_t)((lane & 15) * BPITCH + ((lane >> 4) << 3)) * 2;

    for (int kt = 0; kt < nk; kt++) {
        CP_WAIT1();
        __syncthreads();
        int kf = kt + STAGES - 1;
        if (kf < nk) issue(kf % STAGES, kf);
        CP_COMMIT();

        const int stage = kt % STAGES;
        const uint32_t ab = sb + stage * STG_BYTES;
        const uint32_t bb = ab + 2 * A_STG;

#pragma unroll
        for (int ks = 0; ks < 2; ks++) {
            uint32_t afr[2][2][4];
            uint32_t bfr[BT][4][4];
#pragma unroll
            for (int h = 0; h < 2; h++)
#pragma unroll
                for (int mi = 0; mi < 2; mi++)
                    ldsm4(afr[h][mi],
                          ab + h * A_STG + a_lane_off +
                          (uint32_t)((wm * 32 + mi * 16) * APITCH + ks * 16) * 2);
#pragma unroll
            for (int h = 0; h < BT; h++)
#pragma unroll
                for (int nj = 0; nj < 4; nj++)
                    ldsm4t(bfr[h][nj],
                           bb + h * B_STG + b_lane_off +
                           (uint32_t)(ks * 16 * BPITCH + wn * 64 + nj * 16) * 2);
#pragma unroll
            for (int mi = 0; mi < 2; mi++)
#pragma unroll
                for (int j = 0; j < 8; j++) {
                    const int nj = j >> 1, hf = (j & 1) << 1;
                    mma16816(c[mi][j], afr[0][mi], bfr[0][nj][hf], bfr[0][nj][hf + 1]);
                    if (BT == 2)
                        mma16816(c[mi][j], afr[0][mi], bfr[1][nj][hf], bfr[1][nj][hf + 1]);
                    mma16816(c[mi][j], afr[1][mi], bfr[0][nj][hf], bfr[0][nj][hf + 1]);
                }
        }
        __syncthreads();
    }

    // ---- epilogue ----
#pragma unroll
    for (int mi = 0; mi < 2; mi++) {
        const int r0 = m0 + wm * 32 + mi * 16 + (lane >> 2);
        const float bv0 = has_bias ? bias[r0]     : 0.0f;
        const float bv1 = has_bias ? bias[r0 + 8] : 0.0f;
        float* p0 = C + (size_t)b * sC + (size_t)r0 * ldc + n0 + wn * 64 + (lane & 3) * 2;
        float* p1 = p0 + (size_t)8 * ldc;
#pragma unroll
        for (int j = 0; j < 8; j++) {
            float2 v0 = make_float2(c[mi][j][0] + bv0, c[mi][j][1] + bv0);
            float2 v1 = make_float2(c[mi][j][2] + bv1, c[mi][j][3] + bv1);
            *reinterpret_cast<float2*>(p0 + j * 8) = v0;
            *reinterpret_cast<float2*>(p1 + j * 8) = v1;
        }
    }
}

// ---------------------------------------------------------------------------
// fp16 split conversions
// ---------------------------------------------------------------------------
__global__ void split4(const float* __restrict__ in, __half* __restrict__ hi,
                       __half* __restrict__ lo, int count4,
                       size_t in_bs, size_t out_bs)
{
    size_t b = blockIdx.y;
    int i = blockIdx.x * 256 + threadIdx.x;
    if (i >= count4) return;
    float4 v = reinterpret_cast<const float4*>(in + b * in_bs)[i];
    __half h0 = __float2half_rn(v.x), h1 = __float2half_rn(v.y);
    __half h2 = __float2half_rn(v.z), h3 = __float2half_rn(v.w);
    __half l0 = __float2half_rn(v.x - __half2float(h0));
    __half l1 = __float2half_rn(v.y - __half2float(h1));
    __half l2 = __float2half_rn(v.z - __half2float(h2));
    __half l3 = __float2half_rn(v.w - __half2float(h3));
    __half2* ph = reinterpret_cast<__half2*>(hi + b * out_bs);
    __half2* pl = reinterpret_cast<__half2*>(lo + b * out_bs);
    ph[2 * i]     = __halves2half2(h0, h1);
    ph[2 * i + 1] = __halves2half2(h2, h3);
    pl[2 * i]     = __halves2half2(l0, l1);
    pl[2 * i + 1] = __halves2half2(l2, l3);
}

__global__ void splitW(const float* __restrict__ in, __half* __restrict__ hi,
                       __half* __restrict__ lo)
{
    int i = blockIdx.x * 256 + threadIdx.x;     // 0..896*512-1
    float v = (i < MTOT * CH) ? in[i] : 0.0f;
    __half h = __float2half_rn(v);
    hi[i] = h;
    lo[i] = __float2half_rn(v - __half2float(h));
}

// q [64,HW] per batch (rows 0..63 of Y) -> qT [HW,64] hi/lo
__global__ void qtrans_split(const float* __restrict__ Y, __half* __restrict__ qh,
                             __half* __restrict__ ql)
{
    __shared__ float s[64][65];
    int b = blockIdx.y;
    int i0 = blockIdx.x * 64;
    const float* q = Y + (size_t)b * MPAD * HW;
    for (int u = threadIdx.x; u < 64 * 64; u += 256) {
        int c = u >> 6, i = u & 63;
        s[c][i] = q[(size_t)c * HW + i0 + i];
    }
    __syncthreads();
    for (int u = threadIdx.x; u < 64 * 64; u += 256) {
        int i = u >> 6, c = u & 63;
        float v = s[c][i];
        __half h = __float2half_rn(v);
        size_t o = ((size_t)b * HW + i0 + i) * 64 + c;
        qh[o] = h;
        ql[o] = __float2half_rn(v - __half2float(h));
    }
}

// ---------------------------------------------------------------------------
// Row softmax over E rows of 4096, emits P as single fp16
// ---------------------------------------------------------------------------
__global__ void softmax_p(const float* __restrict__ E, __half* __restrict__ PH)
{
    __shared__ float red[256];
    const size_t row = blockIdx.x;
    const float* rp = E + row * (size_t)HW;
    const int t = threadIdx.x;

    float v[16];
    float m = -1e30f;
#pragma unroll
    for (int i = 0; i < 16; i++) {
        v[i] = rp[t + i * 256];
        m = fmaxf(m, v[i]);
    }
    red[t] = m; __syncthreads();
    for (int s = 128; s > 0; s >>= 1) {
        if (t < s) red[t] = fmaxf(red[t], red[t + s]);
        __syncthreads();
    }
    m = red[0]; __syncthreads();

    float s = 0.f;
#pragma unroll
    for (int i = 0; i < 16; i++) { v[i] = __expf(v[i] - m); s += v[i]; }
    red[t] = s; __syncthreads();
    for (int s2 = 128; s2 > 0; s2 >>= 1) {
        if (t < s2) red[t] += red[t + s2];
        __syncthreads();
    }
    float inv = 1.0f / red[0];
    __half2* ph = reinterpret_cast<__half2*>(PH + row * (size_t)HW);
#pragma unroll
    for (int i = 0; i < 8; i++) {
        float p0 = v[2 * i]     * inv;
        float p1 = v[2 * i + 1] * inv;
        // v[] holds elements t + i*256; pairs (2i,2i+1) are (t+2i*256, t+(2i+1)*256)
        // store individually to keep layout
        PH[row * (size_t)HW + t + (2 * i) * 256]     = __float2half_rn(p0);
        PH[row * (size_t)HW + t + (2 * i + 1) * 256] = __float2half_rn(p1);
    }
    (void)ph;
}

// ---------------------------------------------------------------------------
// SIMT f32x2 GEMM (small K8 accumulate)
// ---------------------------------------------------------------------------
__device__ __forceinline__ unsigned long long pk2(float lo, float hi) {
    unsigned long long r;
    asm("mov.b64 %0, {%1, %2};" : "=l"(r) : "f"(lo), "f"(hi));
    return r;
}
__device__ __forceinline__ unsigned long long fma2(unsigned long long a,
                                                   unsigned long long b,
                                                   unsigned long long c) {
    unsigned long long d;
    asm("fma.rn.f32x2 %0, %1, %2, %3;" : "=l"(d) : "l"(a), "l"(b), "l"(c));
    return d;
}
__device__ __forceinline__ float2 u2f(unsigned long long u) {
    float2 f;
    asm("mov.b64 {%0, %1}, %2;" : "=f"(f.x), "=f"(f.y) : "l"(u));
    return f;
}

__global__ __launch_bounds__(256, 2)
void gemm_acc(const float* __restrict__ A, const float* __restrict__ Bm,
              const float* __restrict__ bias, float* __restrict__ Cm,
              int M, int N, int K, int lda, int ldb, int ldc,
              size_t sA, size_t sB, size_t sC)
{
    __shared__ float As[16][128 + 4];
    __shared__ float Bs[16][128];

    const int b  = blockIdx.z;
    const float* Ab = A + (size_t)b * sA;
    const float* Bb = Bm + (size_t)b * sB;
    float*       Cb = Cm + (size_t)b * sC;

    const int m0 = blockIdx.y * 128;
    const int n0 = blockIdx.x * 128;
    const int t  = threadIdx.x;
    const int tm0 = (t >> 4) << 3;
    const int tn0 = (t & 15) << 3;

    unsigned long long acc[8][4];
#pragma unroll
    for (int i = 0; i < 8; i++)
#pragma unroll
        for (int j = 0; j < 4; j++) acc[i][j] = 0ull;

    for (int k0 = 0; k0 < K; k0 += 16) {
#pragma unroll
        for (int r = 0; r < 2; r++) {
            int idx = t + r * 256;
            int row = idx >> 2;
            int c4  = (idx & 3) << 2;
            float4 v = make_float4(0.f, 0.f, 0.f, 0.f);
            if (m0 + row < M)
                v = *reinterpret_cast<const float4*>(Ab + (size_t)(m0 + row) * lda + k0 + c4);
            As[c4 + 0][row] = v.x; As[c4 + 1][row] = v.y;
            As[c4 + 2][row] = v.z; As[c4 + 3][row] = v.w;
        }
#pragma unroll
        for (int r = 0; r < 2; r++) {
            int idx = t + r * 256;
            int kr  = idx >> 5;
            int n4  = (idx & 31) << 2;
            float4 v = *reinterpret_cast<const float4*>(Bb + (size_t)(k0 + kr) * ldb + n0 + n4);
            *reinterpret_cast<float4*>(&Bs[kr][n4]) = v;
        }
        __syncthreads();
#pragma unroll
        for (int kk = 0; kk < 16; kk++) {
            float4 a0 = *reinterpret_cast<const float4*>(&As[kk][tm0]);
            float4 a1 = *reinterpret_cast<const float4*>(&As[kk][tm0 + 4]);
            ulonglong2 bl0 = *reinterpret_cast<const ulonglong2*>(&Bs[kk][tn0]);
            ulonglong2 bl1 = *reinterpret_cast<const ulonglong2*>(&Bs[kk][tn0 + 4]);
            unsigned long long bv[4] = {bl0.x, bl0.y, bl1.x, bl1.y};
            float av[8] = {a0.x, a0.y, a0.z, a0.w, a1.x, a1.y, a1.z, a1.w};
#pragma unroll
            for (int i = 0; i < 8; i++) {
                unsigned long long a2 = pk2(av[i], av[i]);
#pragma unroll
                for (int j = 0; j < 4; j++) acc[i][j] = fma2(a2, bv[j], acc[i][j]);
            }
        }
        __syncthreads();
    }
#pragma unroll
    for (int i = 0; i < 8; i++) {
        int m = m0 + tm0 + i;
        if (m >= M) continue;
        float bsv = bias[m];
        float* crow = Cb + (size_t)m * ldc + n0 + tn0;
#pragma unroll
        for (int j = 0; j < 4; j++) {
            float2 f = u2f(acc[i][j]);
            float2 o = *reinterpret_cast<const float2*>(crow + j * 2);
            f.x += bsv + o.x; f.y += bsv + o.y;
            *reinterpret_cast<float2*>(crow + j * 2) = f;
        }
    }
}

// ---------------------------------------------------------------------------
// Channel attention kernels (fp32, small)
// ---------------------------------------------------------------------------
__global__ void chan_energy(const float* __restrict__ cq, const float* __restrict__ ck,
                            float* __restrict__ part)
{
    __shared__ float sq[64][65];
    __shared__ float sk[64][65];
    const int b = blockIdx.y;
    const int split = blockIdx.x;
    const float* cqb = cq + (size_t)b * MPAD * HW;
    const float* ckb = ck + (size_t)b * MPAD * HW;
    const int t = threadIdx.x;
    const int p0 = (t >> 4) * 4;
    const int q0 = (t & 15) * 4;

    float acc[4][4];
#pragma unroll
    for (int i = 0; i < 4; i++)
#pragma unroll
        for (int j = 0; j < 4; j++) acc[i][j] = 0.f;

    for (int c = 0; c < 4; c++) {
        const int nb = (split * 4 + c) * 64;
        __syncthreads();
#pragma unroll
        for (int i = 0; i < 16; i++) {
            int idx = t + i * 256;
            int row = idx >> 6, col = idx & 63;
            sq[row][col] = cqb[(size_t)row * HW + nb + col];
            sk[row][col] = ckb[(size_t)row * HW + nb + col];
        }
        __syncthreads();
        for (int nn = 0; nn < 64; nn++) {
            float aq[4], bk[4];
#pragma unroll
            for (int i = 0; i < 4; i++) aq[i] = sq[p0 + i][nn];
#pragma unroll
            for (int j = 0; j < 4; j++) bk[j] = sk[q0 + j][nn];
#pragma unroll
            for (int i = 0; i < 4; i++)
#pragma unroll
                for (int j = 0; j < 4; j++) acc[i][j] += aq[i] * bk[j];
        }
    }
    float* out = part + (size_t)split * (BATCH * 4096) + (size_t)b * 4096;
#pragma unroll
    for (int i = 0; i < 4; i++)
#pragma unroll
        for (int j = 0; j < 4; j++)
            out[(p0 + i) * 64 + (q0 + j)] = acc[i][j];
}

__global__ void reduce_ce(const float* __restrict__ part, float* __restrict__ cE)
{
    int i = blockIdx.x * 256 + threadIdx.x;
    float s = 0.f;
#pragma unroll
    for (int k = 0; k < 16; k++) s += part[(size_t)k * (BATCH * 4096) + i];
    cE[i] = s;
}

__global__ void chan_softmax(float* __restrict__ cE)
{
    __shared__ float red[64];
    const int row = blockIdx.x;
    float* rp = cE + (size_t)row * 64;
    const int t = threadIdx.x;
    float v = rp[t];
    red[t] = v; __syncthreads();
    for (int s = 32; s > 0; s >>= 1) {
        if (t < s) red[t] = fmaxf(red[t], red[t + s]);
        __syncthreads();
    }
    float m = red[0]; __syncthreads();
    float e = __expf(v - m);
    red[t] = e; __syncthreads();
    for (int s = 32; s > 0; s >>= 1) {
        if (t < s) red[t] += red[t + s];
        __syncthreads();
    }
    rp[t] = e / red[0];
}

__global__ void chan_out(const float* __restrict__ cattn, const float* __restrict__ cv,
                         float* __restrict__ cout)
{
    __shared__ float sa[4096];
    const int b = blockIdx.y;
    const int n = blockIdx.x * 256 + threadIdx.x;
    const float* at = cattn + (size_t)b * 4096;
    for (int i = threadIdx.x; i < 4096; i += 256) sa[i] = at[i];
    __syncthreads();

    const float* cvb = cv + (size_t)b * MPAD * HW;
    float acc[64];
#pragma unroll
    for (int p = 0; p < 64; p++) acc[p] = 0.f;
    for (int q = 0; q < 64; q++) {
        float vv = cvb[(size_t)q * HW + n];
#pragma unroll
        for (int p = 0; p < 64; p++) acc[p] += sa[p * 64 + q] * vv;
    }
    float* ob = cout + (size_t)b * CQD * HW;
#pragma unroll
    for (int p = 0; p < 64; p++) ob[(size_t)p * HW + n] = acc[p];
}

// ---------------------------------------------------------------------------
// Launch
// ---------------------------------------------------------------------------
extern "C" void kernel_launch(void* const* d_in, const int* in_sizes, int n_in,
                              void* d_out, int out_size)
{
    (void)in_sizes; (void)n_in; (void)out_size;

    const float* x = (const float*)d_in[0];

    float* S = nullptr;
    cudaGetSymbolAddress((void**)&S, g_scratch);

    float* W   = S + OFF_W;
    float* BI  = S + OFF_BI;
    float* Y   = S + OFF_Y;
    float* E   = S + OFF_E;
    float* CE  = S + OFF_CE;
    float* CEP = S + OFF_CEP;
    float* CO  = S + OFF_CO;
    float* out = (float*)d_out;

    __half* WH  = (__half*)(S + OFF_WH);
    __half* WL  = (__half*)(S + OFF_WL);
    __half* XH  = (__half*)(S + OFF_XH);
    __half* XL  = (__half*)(S + OFF_XL);
    __half* QTH = (__half*)(S + OFF_QTH);
    __half* QTL = (__half*)(S + OFF_QTL);
    __half* KH  = (__half*)(S + OFF_KH);
    __half* KL  = (__half*)(S + OFF_KL);
    __half* VH  = (__half*)(S + OFF_VH);
    __half* VL  = (__half*)(S + OFF_VL);
    __half* PH  = (__half*)(S + OFF_PH);

    // pack fp32 weights + bias
    cudaMemcpyAsync(W +      0, d_in[1],  64  * 512 * sizeof(float), cudaMemcpyDeviceToDevice);
    cudaMemcpyAsync(W +  32768, d_in[3],  64  * 512 * sizeof(float), cudaMemcpyDeviceToDevice);
    cudaMemcpyAsync(W +  65536, d_in[5],  512 * 512 * sizeof(float), cudaMemcpyDeviceToDevice);
    cudaMemcpyAsync(W + 327680, d_in[7],  64  * 512 * sizeof(float), cudaMemcpyDeviceToDevice);
    cudaMemcpyAsync(W + 360448, d_in[9],  64  * 512 * sizeof(float), cudaMemcpyDeviceToDevice);
    cudaMemcpyAsync(W + 393216, d_in[11], 64  * 512 * sizeof(float), cudaMemcpyDeviceToDevice);
    cudaMemcpyAsync(BI +   0, d_in[2],  64  * sizeof(float), cudaMemcpyDeviceToDevice);
    cudaMemcpyAsync(BI +  64, d_in[4],  64  * sizeof(float), cudaMemcpyDeviceToDevice);
    cudaMemcpyAsync(BI + 128, d_in[6],  512 * sizeof(float), cudaMemcpyDeviceToDevice);
    cudaMemcpyAsync(BI + 640, d_in[8],  64  * sizeof(float), cudaMemcpyDeviceToDevice);
    cudaMemcpyAsync(BI + 704, d_in[10], 64  * sizeof(float), cudaMemcpyDeviceToDevice);
    cudaMemcpyAsync(BI + 768, d_in[12], 64  * sizeof(float), cudaMemcpyDeviceToDevice);

    const int SM2 = STAGES * (2 * A_STG + 2 * B_STG);   // 113664
    const int SM1 = STAGES * (2 * A_STG + 1 * B_STG);   // 87552
    cudaFuncSetAttribute(gemm_mma<2>, cudaFuncAttributeMaxDynamicSharedMemorySize, SM2);
    cudaFuncSetAttribute(gemm_mma<1>, cudaFuncAttributeMaxDynamicSharedMemorySize, SM1);

    // fp16 splits of W and x
    splitW<<<(MPAD * CH + 255) / 256, 256>>>(W, WH, WL);
    split4<<<dim3(2048, BATCH), 256>>>(x, XH, XL, 524288, (size_t)CH * HW, (size_t)CH * HW);

    // K1: projections  Y = W @ x + bias   M=896 N=4096 K=512  (3-term)
    gemm_mma<2><<<dim3(32, 7, BATCH), 256, SM2>>>(
        WH, WL, XH, XL, BI, Y, 512, 512, HW, HW,
        (size_t)0, (size_t)CH * HW, (size_t)MPAD * HW, 1);

    // fp16 splits of q (transposed), k, v
    qtrans_split<<<dim3(64, BATCH), 256>>>(Y, QTH, QTL);
    split4<<<dim3(256, BATCH), 256>>>(Y + (size_t)64 * HW, KH, KL, 65536,
                                      (size_t)MPAD * HW, (size_t)64 * HW);
    split4<<<dim3(2048, BATCH), 256>>>(Y + (size_t)128 * HW, VH, VL, 524288,
                                       (size_t)MPAD * HW, (size_t)CH * HW);

    // K2: energy  E = qT @ k   M=4096 N=4096 K=64  (3-term)
    gemm_mma<2><<<dim3(32, 32, BATCH), 256, SM2>>>(
        QTH, QTL, KH, KL, nullptr, E, 64, 64, HW, HW,
        (size_t)HW * 64, (size_t)64 * HW, (size_t)HW * HW, 0);

    // K3: softmax -> P (single fp16)
    softmax_p<<<BATCH * HW, 256>>>(E, PH);

    // K4: pos_out = v @ P   M=512 N=4096 K=4096  (2-term, B single)
    gemm_mma<1><<<dim3(32, 4, BATCH), 256, SM1>>>(
        VH, VL, PH, nullptr, nullptr, out, HW, HW, HW, HW,
        (size_t)CH * HW, (size_t)HW * HW, (size_t)CH * HW, 0);

    // Channel path (fp32, Y rows 640/704/768)
    chan_energy<<<dim3(16, BATCH), 256>>>(Y + (size_t)640 * HW, Y + (size_t)704 * HW, CEP);
    reduce_ce<<<128, 256>>>(CEP, CE);
    chan_softmax<<<BATCH * 64, 64>>>(CE);
    chan_out<<<dim3(16, BATCH), 256>>>(CE, Y + (size_t)768 * HW, CO);

    // K8: d_out += co_w @ c_out + co_b   M=512 N=4096 K=64 (SIMT)
    gemm_acc<<<dim3(32, 4, BATCH), 256>>>(
        (const float*)d_in[13], CO, (const float*)d_in[14], out,
        CH, HW, CQD, CQD, HW, HW,
        (size_t)0, (size_t)CQD * HW, (size_t)CH * HW);
}

// round 5
// speedup vs baseline: 3.4574x; 1.2860x over previous
#include <cuda_runtime.h>
#include <cuda_fp16.h>
#include <cstdint>
#include <cstddef>

// ---------------------------------------------------------------------------
// Problem constants
// ---------------------------------------------------------------------------
#define BATCH 8
#define CH    512
#define CQD   64
#define HW    4096
#define MTOT  832          // packed projection rows (pq,pk,pv,cq,ck,cv)
#define MPAD  896          // padded to multiple of 128

// scratch layout (float offsets)
#define OFF_W    0u            // packed fp32 weights [832,512]
#define OFF_BI   425984u       // packed bias
#define OFF_WH   427008u       // W hi fp16 [896,512]
#define OFF_WL   656384u
#define OFF_XH   885760u       // x hi fp16 [8,512,4096]
#define OFF_XL   9274368u
#define OFF_Y    17662976u     // fp32 projections [8,896,4096] (q + channel rows)
#define OFF_QTH  47023104u     // qT hi fp16 [8,4096,64]
#define OFF_QTL  48071680u
#define OFF_KH   49120256u     // k hi fp16 [8,64,4096]
#define OFF_KL   50168832u
#define OFF_VH   51217408u     // v fp16 [8,512,4096]
#define OFF_E    59606016u     // fp32 energy [8,4096,4096]
#define OFF_PH   193823744u    // P fp16 [8,4096,4096]
#define OFF_CE   260932608u
#define OFF_CEP  260965376u
#define OFF_CO   261489664u
#define SCRATCH_FLOATS 263586816u

__device__ float g_scratch[SCRATCH_FLOATS];

// ---------------------------------------------------------------------------
// PTX helpers (base-ISA only: mma.sync / ldmatrix / cp.async)
// ---------------------------------------------------------------------------
__device__ __forceinline__ uint32_t smem_to_u32(const void* p) {
    uint32_t a;
    asm("{ .reg .u64 t; cvta.to.shared.u64 t, %1; cvt.u32.u64 %0, t; }" : "=r"(a) : "l"(p));
    return a;
}

__device__ __forceinline__ void ldsm4(uint32_t* r, uint32_t addr) {
    asm volatile("ldmatrix.sync.aligned.m8n8.x4.shared.b16 {%0,%1,%2,%3}, [%4];"
                 : "=r"(r[0]), "=r"(r[1]), "=r"(r[2]), "=r"(r[3]) : "r"(addr));
}
__device__ __forceinline__ void ldsm4t(uint32_t* r, uint32_t addr) {
    asm volatile("ldmatrix.sync.aligned.m8n8.x4.trans.shared.b16 {%0,%1,%2,%3}, [%4];"
                 : "=r"(r[0]), "=r"(r[1]), "=r"(r[2]), "=r"(r[3]) : "r"(addr));
}
__device__ __forceinline__ void mma16816(float* c, const uint32_t* a,
                                         uint32_t b0, uint32_t b1) {
    asm volatile("mma.sync.aligned.m16n8k16.row.col.f32.f16.f16.f32 "
                 "{%0,%1,%2,%3}, {%4,%5,%6,%7}, {%8,%9}, {%0,%1,%2,%3};"
                 : "+f"(c[0]), "+f"(c[1]), "+f"(c[2]), "+f"(c[3])
                 : "r"(a[0]), "r"(a[1]), "r"(a[2]), "r"(a[3]), "r"(b0), "r"(b1));
}
__device__ __forceinline__ void cp16(uint32_t dst, const void* src) {
    asm volatile("cp.async.cg.shared.global [%0], [%1], 16;" :: "r"(dst), "l"(src));
}
#define CP_COMMIT() asm volatile("cp.async.commit_group;" ::: "memory")
#define CP_WAIT1()  asm volatile("cp.async.wait_group 1;"  ::: "memory")

// ---------------------------------------------------------------------------
// fp16-split GEMM via mma.sync (HMMA), templated on term counts:
//   AT=2,BT=2:  C = Ah@Bh + Ah@Bl + Al@Bh   (~2^-22 precision)
//   AT=1,BT=1:  C = A@B                     (plain fp16)
// A: [M,K] row-major fp16. B: [K,N] row-major fp16. M,N mult of 128, K of 32.
// CTA tile 128x128, BK=32, 3 cp.async stages, 8 warps (4m x 2n).
// Optional routed epilogue (KHo != nullptr): K1 projection fusion --
//   rows [0,64)+[640,832) -> fp32 C;  [64,128) -> KH/KL split;
//   [128,640) -> VH single fp16;  rows >= MTOT skipped.
// ---------------------------------------------------------------------------
#define STAGES  3
#define APITCH  40                      // fp16 elems per A smem row (80B)
#define BPITCH  136                     // fp16 elems per B smem row (272B)
#define A_STG   (128 * APITCH * 2)      // 10240 B per term buffer
#define B_STG   (32 * BPITCH * 2)       // 8704 B

template<int AT, int BT>
__global__ void __launch_bounds__(256, (AT == 1) ? 2 : 1) gemm_mma(
    const __half* __restrict__ Ah, const __half* __restrict__ Al,
    const __half* __restrict__ Bh, const __half* __restrict__ Bl,
    const float* __restrict__ bias, float* __restrict__ C,
    int K, int lda, int ldb, int ldc,
    size_t sA, size_t sB, size_t sC, int has_bias,
    __half* __restrict__ KHo, __half* __restrict__ KLo, __half* __restrict__ VHo)
{
    constexpr int STG_BYTES = AT * A_STG + BT * B_STG;
    extern __shared__ char smem[];
    const uint32_t sb = smem_to_u32(smem);
    const int tid  = threadIdx.x;
    const int w    = tid >> 5, lane = tid & 31;
    const int wm   = w & 3,    wn   = w >> 2;
    const int b    = blockIdx.z;
    const int m0   = blockIdx.y * 128, n0 = blockIdx.x * 128;

    const __half* Ag[AT];
    Ag[0] = Ah + (size_t)b * sA + (size_t)m0 * lda;
    if (AT == 2) Ag[1] = Al + (size_t)b * sA + (size_t)m0 * lda;
    const __half* Bg[BT];
    Bg[0] = Bh + (size_t)b * sB + n0;
    if (BT == 2) Bg[1] = Bl + (size_t)b * sB + n0;

    const int nk = K >> 5;

    const int a_row = tid >> 2, a_ch = (tid & 3) << 3;     // 64 rows / iter
    const int b_row = tid >> 4, b_ch = (tid & 15) << 3;    // 16 rows / iter

    auto issue = [&](int stage, int kt) {
        const uint32_t base = sb + stage * STG_BYTES;
        const int k0 = kt << 5;
#pragma unroll
        for (int h = 0; h < AT; h++) {
            const __half* asrc = Ag[h] + k0;
            const uint32_t adst = base + h * A_STG;
#pragma unroll
            for (int r = 0; r < 2; r++) {
                int row = a_row + r * 64;
                cp16(adst + (uint32_t)(row * APITCH + a_ch) * 2,
                     asrc + (size_t)row * lda + a_ch);
            }
        }
#pragma unroll
        for (int h = 0; h < BT; h++) {
            const __half* bsrc = Bg[h];
            const uint32_t bdst = base + AT * A_STG + h * B_STG;
#pragma unroll
            for (int r = 0; r < 2; r++) {
                int row = b_row + r * 16;
                cp16(bdst + (uint32_t)(row * BPITCH + b_ch) * 2,
                     bsrc + (size_t)(k0 + row) * ldb + b_ch);
            }
        }
    };

    float c[2][8][4];
#pragma unroll
    for (int mi = 0; mi < 2; mi++)
#pragma unroll
        for (int j = 0; j < 8; j++)
#pragma unroll
            for (int q = 0; q < 4; q++) c[mi][j][q] = 0.0f;

    issue(0, 0); CP_COMMIT();
    if (nk > 1) issue(1, 1);
    CP_COMMIT();

    const uint32_t a_lane_off = (uint32_t)((lane & 15) * APITCH + ((lane >> 4) << 3)) * 2;
    const uint32_t b_lane_off = (uint32_t)((lane & 15) * BPITCH + ((lane >> 4) << 3)) * 2;

    for (int kt = 0; kt < nk; kt++) {
        CP_WAIT1();
        __syncthreads();
        int kf = kt + STAGES - 1;
        if (kf < nk) issue(kf % STAGES, kf);
        CP_COMMIT();

        const int stage = kt % STAGES;
        const uint32_t ab = sb + stage * STG_BYTES;
        const uint32_t bb = ab + AT * A_STG;

#pragma unroll
        for (int ks = 0; ks < 2; ks++) {
            uint32_t afr[AT][2][4];
            uint32_t bfr[BT][4][4];
#pragma unroll
            for (int h = 0; h < AT; h++)
#pragma unroll
                for (int mi = 0; mi < 2; mi++)
                    ldsm4(afr[h][mi],
                          ab + h * A_STG + a_lane_off +
                          (uint32_t)((wm * 32 + mi * 16) * APITCH + ks * 16) * 2);
#pragma unroll
            for (int h = 0; h < BT; h++)
#pragma unroll
                for (int nj = 0; nj < 4; nj++)
                    ldsm4t(bfr[h][nj],
                           bb + h * B_STG + b_lane_off +
                           (uint32_t)(ks * 16 * BPITCH + wn * 64 + nj * 16) * 2);
#pragma unroll
            for (int mi = 0; mi < 2; mi++)
#pragma unroll
                for (int j = 0; j < 8; j++) {
                    const int nj = j >> 1, hf = (j & 1) << 1;
                    mma16816(c[mi][j], afr[0][mi], bfr[0][nj][hf], bfr[0][nj][hf + 1]);
                    if (BT == 2)
                        mma16816(c[mi][j], afr[0][mi], bfr[1][nj][hf], bfr[1][nj][hf + 1]);
                    if (AT == 2)
                        mma16816(c[mi][j], afr[1][mi], bfr[0][nj][hf], bfr[0][nj][hf + 1]);
                }
        }
        __syncthreads();
    }

    // ---- epilogue ----
    const int colbase = n0 + wn * 64 + (lane & 3) * 2;
    if (KHo != nullptr) {
        // routed projection epilogue (K1)
#pragma unroll
        for (int mi = 0; mi < 2; mi++)
#pragma unroll
            for (int rr = 0; rr < 2; rr++) {
                const int row = m0 + wm * 32 + mi * 16 + (lane >> 2) + rr * 8;
                if (row >= MTOT) continue;
                const float bv = bias[row];
                if (row < 64 || row >= 640) {
                    float* p = C + (size_t)b * sC + (size_t)row * ldc + colbase;
#pragma unroll
                    for (int j = 0; j < 8; j++)
                        *reinterpret_cast<float2*>(p + j * 8) =
                            make_float2(c[mi][j][rr * 2] + bv, c[mi][j][rr * 2 + 1] + bv);
                } else if (row < 128) {
                    __half* ph = KHo + ((size_t)b * 64 + (row - 64)) * HW + colbase;
                    __half* pl = KLo + ((size_t)b * 64 + (row - 64)) * HW + colbase;
#pragma unroll
                    for (int j = 0; j < 8; j++) {
                        float v0 = c[mi][j][rr * 2] + bv, v1 = c[mi][j][rr * 2 + 1] + bv;
                        __half h0 = __float2half_rn(v0), h1 = __float2half_rn(v1);
                        *reinterpret_cast<__half2*>(ph + j * 8) = __halves2half2(h0, h1);
                        *reinterpret_cast<__half2*>(pl + j * 8) = __halves2half2(
                            __float2half_rn(v0 - __half2float(h0)),
                            __float2half_rn(v1 - __half2float(h1)));
                    }
                } else {
                    __half* ph = VHo + ((size_t)b * 512 + (row - 128)) * HW + colbase;
#pragma unroll
                    for (int j = 0; j < 8; j++)
                        *reinterpret_cast<__half2*>(ph + j * 8) = __halves2half2(
                            __float2half_rn(c[mi][j][rr * 2] + bv),
                            __float2half_rn(c[mi][j][rr * 2 + 1] + bv));
                }
            }
    } else {
#pragma unroll
        for (int mi = 0; mi < 2; mi++) {
            const int r0 = m0 + wm * 32 + mi * 16 + (lane >> 2);
            const float bv0 = has_bias ? bias[r0]     : 0.0f;
            const float bv1 = has_bias ? bias[r0 + 8] : 0.0f;
            float* p0 = C + (size_t)b * sC + (size_t)r0 * ldc + colbase;
            float* p1 = p0 + (size_t)8 * ldc;
#pragma unroll
            for (int j = 0; j < 8; j++) {
                *reinterpret_cast<float2*>(p0 + j * 8) =
                    make_float2(c[mi][j][0] + bv0, c[mi][j][1] + bv0);
                *reinterpret_cast<float2*>(p1 + j * 8) =
                    make_float2(c[mi][j][2] + bv1, c[mi][j][3] + bv1);
            }
        }
    }
}

// ---------------------------------------------------------------------------
// fp16 split conversions
// ---------------------------------------------------------------------------
__global__ void split4(const float* __restrict__ in, __half* __restrict__ hi,
                       __half* __restrict__ lo, int count4,
                       size_t in_bs, size_t out_bs)
{
    size_t b = blockIdx.y;
    int i = blockIdx.x * 256 + threadIdx.x;
    if (i >= count4) return;
    float4 v = reinterpret_cast<const float4*>(in + b * in_bs)[i];
    __half h0 = __float2half_rn(v.x), h1 = __float2half_rn(v.y);
    __half h2 = __float2half_rn(v.z), h3 = __float2half_rn(v.w);
    __half l0 = __float2half_rn(v.x - __half2float(h0));
    __half l1 = __float2half_rn(v.y - __half2float(h1));
    __half l2 = __float2half_rn(v.z - __half2float(h2));
    __half l3 = __float2half_rn(v.w - __half2float(h3));
    __half2* ph = reinterpret_cast<__half2*>(hi + b * out_bs);
    __half2* pl = reinterpret_cast<__half2*>(lo + b * out_bs);
    ph[2 * i]     = __halves2half2(h0, h1);
    ph[2 * i + 1] = __halves2half2(h2, h3);
    pl[2 * i]     = __halves2half2(l0, l1);
    pl[2 * i + 1] = __halves2half2(l2, l3);
}

__global__ void splitW(const float* __restrict__ in, __half* __restrict__ hi,
                       __half* __restrict__ lo)
{
    int i = blockIdx.x * 256 + threadIdx.x;     // 0..896*512-1
    float v = (i < MTOT * CH) ? in[i] : 0.0f;
    __half h = __float2half_rn(v);
    hi[i] = h;
    lo[i] = __float2half_rn(v - __half2float(h));
}

// q [64,HW] per batch (rows 0..63 of Y) -> qT [HW,64] hi/lo
__global__ void qtrans_split(const float* __restrict__ Y, __half* __restrict__ qh,
                             __half* __restrict__ ql)
{
    __shared__ float s[64][65];
    int b = blockIdx.y;
    int i0 = blockIdx.x * 64;
    const float* q = Y + (size_t)b * MPAD * HW;
    for (int u = threadIdx.x; u < 64 * 64; u += 256) {
        int c = u >> 6, i = u & 63;
        s[c][i] = q[(size_t)c * HW + i0 + i];
    }
    __syncthreads();
    for (int u = threadIdx.x; u < 64 * 64; u += 256) {
        int i = u >> 6, c = u & 63;
        float v = s[c][i];
        __half h = __float2half_rn(v);
        size_t o = ((size_t)b * HW + i0 + i) * 64 + c;
        qh[o] = h;
        ql[o] = __float2half_rn(v - __half2float(h));
    }
}

// ---------------------------------------------------------------------------
// Row softmax over E rows of 4096, emits P as single fp16
// ---------------------------------------------------------------------------
__global__ void softmax_p(const float* __restrict__ E, __half* __restrict__ PH)
{
    __shared__ float red[256];
    const size_t row = blockIdx.x;
    const float* rp = E + row * (size_t)HW;
    const int t = threadIdx.x;

    float v[16];
    float m = -1e30f;
#pragma unroll
    for (int i = 0; i < 16; i++) {
        v[i] = rp[t + i * 256];
        m = fmaxf(m, v[i]);
    }
    red[t] = m; __syncthreads();
    for (int s = 128; s > 0; s >>= 1) {
        if (t < s) red[t] = fmaxf(red[t], red[t + s]);
        __syncthreads();
    }
    m = red[0]; __syncthreads();

    float s = 0.f;
#pragma unroll
    for (int i = 0; i < 16; i++) { v[i] = __expf(v[i] - m); s += v[i]; }
    red[t] = s; __syncthreads();
    for (int s2 = 128; s2 > 0; s2 >>= 1) {
        if (t < s2) red[t] += red[t + s2];
        __syncthreads();
    }
    float inv = 1.0f / red[0];
#pragma unroll
    for (int i = 0; i < 16; i++)
        PH[row * (size_t)HW + t + i * 256] = __float2half_rn(v[i] * inv);
}

// ---------------------------------------------------------------------------
// SIMT f32x2 GEMM (small K8 accumulate)
// ---------------------------------------------------------------------------
__device__ __forceinline__ unsigned long long pk2(float lo, float hi) {
    unsigned long long r;
    asm("mov.b64 %0, {%1, %2};" : "=l"(r) : "f"(lo), "f"(hi));
    return r;
}
__device__ __forceinline__ unsigned long long fma2(unsigned long long a,
                                                   unsigned long long b,
                                                   unsigned long long c) {
    unsigned long long d;
    asm("fma.rn.f32x2 %0, %1, %2, %3;" : "=l"(d) : "l"(a), "l"(b), "l"(c));
    return d;
}
__device__ __forceinline__ float2 u2f(unsigned long long u) {
    float2 f;
    asm("mov.b64 {%0, %1}, %2;" : "=f"(f.x), "=f"(f.y) : "l"(u));
    return f;
}

__global__ __launch_bounds__(256, 2)
void gemm_acc(const float* __restrict__ A, const float* __restrict__ Bm,
              const float* __restrict__ bias, float* __restrict__ Cm,
              int M, int N, int K, int lda, int ldb, int ldc,
              size_t sA, size_t sB, size_t sC)
{
    __shared__ float As[16][128 + 4];
    __shared__ float Bs[16][128];

    const int b  = blockIdx.z;
    const float* Ab = A + (size_t)b * sA;
    const float* Bb = Bm + (size_t)b * sB;
    float*       Cb = Cm + (size_t)b * sC;

    const int m0 = blockIdx.y * 128;
    const int n0 = blockIdx.x * 128;
    const int t  = threadIdx.x;
    const int tm0 = (t >> 4) << 3;
    const int tn0 = (t & 15) << 3;

    unsigned long long acc[8][4];
#pragma unroll
    for (int i = 0; i < 8; i++)
#pragma unroll
        for (int j = 0; j < 4; j++) acc[i][j] = 0ull;

    for (int k0 = 0; k0 < K; k0 += 16) {
#pragma unroll
        for (int r = 0; r < 2; r++) {
            int idx = t + r * 256;
            int row = idx >> 2;
            int c4  = (idx & 3) << 2;
            float4 v = make_float4(0.f, 0.f, 0.f, 0.f);
            if (m0 + row < M)
                v = *reinterpret_cast<const float4*>(Ab + (size_t)(m0 + row) * lda + k0 + c4);
            As[c4 + 0][row] = v.x; As[c4 + 1][row] = v.y;
            As[c4 + 2][row] = v.z; As[c4 + 3][row] = v.w;
        }
#pragma unroll
        for (int r = 0; r < 2; r++) {
            int idx = t + r * 256;
            int kr  = idx >> 5;
            int n4  = (idx & 31) << 2;
            float4 v = *reinterpret_cast<const float4*>(Bb + (size_t)(k0 + kr) * ldb + n0 + n4);
            *reinterpret_cast<float4*>(&Bs[kr][n4]) = v;
        }
        __syncthreads();
#pragma unroll
        for (int kk = 0; kk < 16; kk++) {
            float4 a0 = *reinterpret_cast<const float4*>(&As[kk][tm0]);
            float4 a1 = *reinterpret_cast<const float4*>(&As[kk][tm0 + 4]);
            ulonglong2 bl0 = *reinterpret_cast<const ulonglong2*>(&Bs[kk][tn0]);
            ulonglong2 bl1 = *reinterpret_cast<const ulonglong2*>(&Bs[kk][tn0 + 4]);
            unsigned long long bv[4] = {bl0.x, bl0.y, bl1.x, bl1.y};
            float av[8] = {a0.x, a0.y, a0.z, a0.w, a1.x, a1.y, a1.z, a1.w};
#pragma unroll
            for (int i = 0; i < 8; i++) {
                unsigned long long a2 = pk2(av[i], av[i]);
#pragma unroll
                for (int j = 0; j < 4; j++) acc[i][j] = fma2(a2, bv[j], acc[i][j]);
            }
        }
        __syncthreads();
    }
#pragma unroll
    for (int i = 0; i < 8; i++) {
        int m = m0 + tm0 + i;
        if (m >= M) continue;
        float bsv = bias[m];
        float* crow = Cb + (size_t)m * ldc + n0 + tn0;
#pragma unroll
        for (int j = 0; j < 4; j++) {
            float2 f = u2f(acc[i][j]);
            float2 o = *reinterpret_cast<const float2*>(crow + j * 2);
            f.x += bsv + o.x; f.y += bsv + o.y;
            *reinterpret_cast<float2*>(crow + j * 2) = f;
        }
    }
}

// ---------------------------------------------------------------------------
// Channel attention kernels (fp32, small)
// ---------------------------------------------------------------------------
__global__ void chan_energy(const float* __restrict__ cq, const float* __restrict__ ck,
                            float* __restrict__ part)
{
    __shared__ float sq[64][65];
    __shared__ float sk[64][65];
    const int b = blockIdx.y;
    const int split = blockIdx.x;
    const float* cqb = cq + (size_t)b * MPAD * HW;
    const float* ckb = ck + (size_t)b * MPAD * HW;
    const int t = threadIdx.x;
    const int p0 = (t >> 4) * 4;
    const int q0 = (t & 15) * 4;

    float acc[4][4];
#pragma unroll
    for (int i = 0; i < 4; i++)
#pragma unroll
        for (int j = 0; j < 4; j++) acc[i][j] = 0.f;

    for (int c = 0; c < 4; c++) {
        const int nb = (split * 4 + c) * 64;
        __syncthreads();
#pragma unroll
        for (int i = 0; i < 16; i++) {
            int idx = t + i * 256;
            int row = idx >> 6, col = idx & 63;
            sq[row][col] = cqb[(size_t)row * HW + nb + col];
            sk[row][col] = ckb[(size_t)row * HW + nb + col];
        }
        __syncthreads();
        for (int nn = 0; nn < 64; nn++) {
            float aq[4], bk[4];
#pragma unroll
            for (int i = 0; i < 4; i++) aq[i] = sq[p0 + i][nn];
#pragma unroll
            for (int j = 0; j < 4; j++) bk[j] = sk[q0 + j][nn];
#pragma unroll
            for (int i = 0; i < 4; i++)
#pragma unroll
                for (int j = 0; j < 4; j++) acc[i][j] += aq[i] * bk[j];
        }
    }
    float* out = part + (size_t)split * (BATCH * 4096) + (size_t)b * 4096;
#pragma unroll
    for (int i = 0; i < 4; i++)
#pragma unroll
        for (int j = 0; j < 4; j++)
            out[(p0 + i) * 64 + (q0 + j)] = acc[i][j];
}

__global__ void reduce_ce(const float* __restrict__ part, float* __restrict__ cE)
{
    int i = blockIdx.x * 256 + threadIdx.x;
    float s = 0.f;
#pragma unroll
    for (int k = 0; k < 16; k++) s += part[(size_t)k * (BATCH * 4096) + i];
    cE[i] = s;
}

__global__ void chan_softmax(float* __restrict__ cE)
{
    __shared__ float red[64];
    const int row = blockIdx.x;
    float* rp = cE + (size_t)row * 64;
    const int t = threadIdx.x;
    float v = rp[t];
    red[t] = v; __syncthreads();
    for (int s = 32; s > 0; s >>= 1) {
        if (t < s) red[t] = fmaxf(red[t], red[t + s]);
        __syncthreads();
    }
    float m = red[0]; __syncthreads();
    float e = __expf(v - m);
    red[t] = e; __syncthreads();
    for (int s = 32; s > 0; s >>= 1) {
        if (t < s) red[t] += red[t + s];
        __syncthreads();
    }
    rp[t] = e / red[0];
}

__global__ void chan_out(const float* __restrict__ cattn, const float* __restrict__ cv,
                         float* __restrict__ cout)
{
    __shared__ float sa[4096];
    const int b = blockIdx.y;
    const int n = blockIdx.x * 256 + threadIdx.x;
    const float* at = cattn + (size_t)b * 4096;
    for (int i = threadIdx.x; i < 4096; i += 256) sa[i] = at[i];
    __syncthreads();

    const float* cvb = cv + (size_t)b * MPAD * HW;
    float acc[64];
#pragma unroll
    for (int p = 0; p < 64; p++) acc[p] = 0.f;
    for (int q = 0; q < 64; q++) {
        float vv = cvb[(size_t)q * HW + n];
#pragma unroll
        for (int p = 0; p < 64; p++) acc[p] += sa[p * 64 + q] * vv;
    }
    float* ob = cout + (size_t)b * CQD * HW;
#pragma unroll
    for (int p = 0; p < 64; p++) ob[(size_t)p * HW + n] = acc[p];
}

// ---------------------------------------------------------------------------
// Launch
// ---------------------------------------------------------------------------
extern "C" void kernel_launch(void* const* d_in, const int* in_sizes, int n_in,
                              void* d_out, int out_size)
{
    (void)in_sizes; (void)n_in; (void)out_size;

    const float* x = (const float*)d_in[0];

    float* S = nullptr;
    cudaGetSymbolAddress((void**)&S, g_scratch);

    float* W   = S + OFF_W;
    float* BI  = S + OFF_BI;
    float* Y   = S + OFF_Y;
    float* E   = S + OFF_E;
    float* CE  = S + OFF_CE;
    float* CEP = S + OFF_CEP;
    float* CO  = S + OFF_CO;
    float* out = (float*)d_out;

    __half* WH  = (__half*)(S + OFF_WH);
    __half* WL  = (__half*)(S + OFF_WL);
    __half* XH  = (__half*)(S + OFF_XH);
    __half* XL  = (__half*)(S + OFF_XL);
    __half* QTH = (__half*)(S + OFF_QTH);
    __half* QTL = (__half*)(S + OFF_QTL);
    __half* KH  = (__half*)(S + OFF_KH);
    __half* KL  = (__half*)(S + OFF_KL);
    __half* VH  = (__half*)(S + OFF_VH);
    __half* PH  = (__half*)(S + OFF_PH);

    // pack fp32 weights + bias
    cudaMemcpyAsync(W +      0, d_in[1],  64  * 512 * sizeof(float), cudaMemcpyDeviceToDevice);
    cudaMemcpyAsync(W +  32768, d_in[3],  64  * 512 * sizeof(float), cudaMemcpyDeviceToDevice);
    cudaMemcpyAsync(W +  65536, d_in[5],  512 * 512 * sizeof(float), cudaMemcpyDeviceToDevice);
    cudaMemcpyAsync(W + 327680, d_in[7],  64  * 512 * sizeof(float), cudaMemcpyDeviceToDevice);
    cudaMemcpyAsync(W + 360448, d_in[9],  64  * 512 * sizeof(float), cudaMemcpyDeviceToDevice);
    cudaMemcpyAsync(W + 393216, d_in[11], 64  * 512 * sizeof(float), cudaMemcpyDeviceToDevice);
    cudaMemcpyAsync(BI +   0, d_in[2],  64  * sizeof(float), cudaMemcpyDeviceToDevice);
    cudaMemcpyAsync(BI +  64, d_in[4],  64  * sizeof(float), cudaMemcpyDeviceToDevice);
    cudaMemcpyAsync(BI + 128, d_in[6],  512 * sizeof(float), cudaMemcpyDeviceToDevice);
    cudaMemcpyAsync(BI + 640, d_in[8],  64  * sizeof(float), cudaMemcpyDeviceToDevice);
    cudaMemcpyAsync(BI + 704, d_in[10], 64  * sizeof(float), cudaMemcpyDeviceToDevice);
    cudaMemcpyAsync(BI + 768, d_in[12], 64  * sizeof(float), cudaMemcpyDeviceToDevice);

    const int SM22 = STAGES * (2 * A_STG + 2 * B_STG);   // 113664
    const int SM11 = STAGES * (1 * A_STG + 1 * B_STG);   // 56832
    cudaFuncSetAttribute(gemm_mma<2, 2>, cudaFuncAttributeMaxDynamicSharedMemorySize, SM22);
    cudaFuncSetAttribute(gemm_mma<1, 1>, cudaFuncAttributeMaxDynamicSharedMemorySize, SM11);

    // fp16 splits of W and x
    splitW<<<(MPAD * CH + 255) / 256, 256>>>(W, WH, WL);
    split4<<<dim3(2048, BATCH), 256>>>(x, XH, XL, 524288, (size_t)CH * HW, (size_t)CH * HW);

    // K1: projections, routed epilogue -> Y fp32 (q+channel rows), KH/KL, VH
    gemm_mma<2, 2><<<dim3(32, 7, BATCH), 256, SM22>>>(
        WH, WL, XH, XL, BI, Y, 512, 512, HW, HW,
        (size_t)0, (size_t)CH * HW, (size_t)MPAD * HW, 1, KH, KL, VH);

    // q (rows 0..63 of Y) transpose + split
    qtrans_split<<<dim3(64, BATCH), 256>>>(Y, QTH, QTL);

    // K2: energy  E = qT @ k   M=4096 N=4096 K=64  (3-term)
    gemm_mma<2, 2><<<dim3(32, 32, BATCH), 256, SM22>>>(
        QTH, QTL, KH, KL, nullptr, E, 64, 64, HW, HW,
        (size_t)HW * 64, (size_t)64 * HW, (size_t)HW * HW, 0,
        nullptr, nullptr, nullptr);

    // K3: softmax -> P (single fp16)
    softmax_p<<<BATCH * HW, 256>>>(E, PH);

    // K4: pos_out = v @ P   M=512 N=4096 K=4096  (single-term fp16)
    gemm_mma<1, 1><<<dim3(32, 4, BATCH), 256, SM11>>>(
        VH, nullptr, PH, nullptr, nullptr, out, HW, HW, HW, HW,
        (size_t)CH * HW, (size_t)HW * HW, (size_t)CH * HW, 0,
        nullptr, nullptr, nullptr);

    // Channel path (fp32, Y rows 640/704/768)
    chan_energy<<<dim3(16, BATCH), 256>>>(Y + (size_t)640 * HW, Y + (size_t)704 * HW, CEP);
    reduce_ce<<<128, 256>>>(CEP, CE);
    chan_softmax<<<BATCH * 64, 64>>>(CE);
    chan_out<<<dim3(16, BATCH), 256>>>(CE, Y + (size_t)768 * HW, CO);

    // K8: d_out += co_w @ c_out + co_b   M=512 N=4096 K=64 (SIMT)
    gemm_acc<<<dim3(32, 4, BATCH), 256>>>(
        (const float*)d_in[13], CO, (const float*)d_in[14], out,
        CH, HW, CQD, CQD, HW, HW,
        (size_t)0, (size_t)CQD * HW, (size_t)CH * HW);
}

// round 6
// speedup vs baseline: 3.6435x; 1.0538x over previous
#include <cuda_runtime.h>
#include <cuda_fp16.h>
#include <cstdint>
#include <cstddef>

// ---------------------------------------------------------------------------
// Problem constants
// ---------------------------------------------------------------------------
#define BATCH 8
#define CH    512
#define CQD   64
#define HW    4096
#define MTOT  832          // packed projection rows (pq,pk,pv,cq,ck,cv)
#define MPAD  896          // padded to multiple of 128

// scratch layout (float offsets)
#define OFF_W    0u            // packed fp32 weights [832,512]
#define OFF_BI   425984u       // packed bias
#define OFF_WH   427008u       // W hi fp16 [896,512]
#define OFF_WL   656384u
#define OFF_XH   885760u       // x hi fp16 [8,512,4096]
#define OFF_XL   9274368u
#define OFF_Y    17662976u     // fp32 projections [8,896,4096] (q + channel rows)
#define OFF_QTH  47023104u     // qT hi fp16 [8,4096,64]
#define OFF_QTL  48071680u
#define OFF_KH   49120256u     // k hi fp16 [8,64,4096]
#define OFF_KL   50168832u
#define OFF_VH   51217408u     // v fp16 [8,512,4096] (later scaled by 1/Z)
#define OFF_PH   59606016u     // PE = exp(E-8) fp16 [8,4096,4096]
#define OFF_PART 126714880u    // row-sum partials fp32 [8,32,4096]
#define OFF_ZINV 127763456u    // 1/Z fp32 [8,4096]
#define OFF_CE   127796224u
#define OFF_CEP  127828992u
#define OFF_CO   128353280u
#define SCRATCH_FLOATS 130450432u

__device__ float g_scratch[SCRATCH_FLOATS];

// ---------------------------------------------------------------------------
// PTX helpers (base-ISA only: mma.sync / ldmatrix / cp.async)
// ---------------------------------------------------------------------------
__device__ __forceinline__ uint32_t smem_to_u32(const void* p) {
    uint32_t a;
    asm("{ .reg .u64 t; cvta.to.shared.u64 t, %1; cvt.u32.u64 %0, t; }" : "=r"(a) : "l"(p));
    return a;
}

__device__ __forceinline__ void ldsm4(uint32_t* r, uint32_t addr) {
    asm volatile("ldmatrix.sync.aligned.m8n8.x4.shared.b16 {%0,%1,%2,%3}, [%4];"
                 : "=r"(r[0]), "=r"(r[1]), "=r"(r[2]), "=r"(r[3]) : "r"(addr));
}
__device__ __forceinline__ void ldsm4t(uint32_t* r, uint32_t addr) {
    asm volatile("ldmatrix.sync.aligned.m8n8.x4.trans.shared.b16 {%0,%1,%2,%3}, [%4];"
                 : "=r"(r[0]), "=r"(r[1]), "=r"(r[2]), "=r"(r[3]) : "r"(addr));
}
__device__ __forceinline__ void mma16816(float* c, const uint32_t* a,
                                         uint32_t b0, uint32_t b1) {
    asm volatile("mma.sync.aligned.m16n8k16.row.col.f32.f16.f16.f32 "
                 "{%0,%1,%2,%3}, {%4,%5,%6,%7}, {%8,%9}, {%0,%1,%2,%3};"
                 : "+f"(c[0]), "+f"(c[1]), "+f"(c[2]), "+f"(c[3])
                 : "r"(a[0]), "r"(a[1]), "r"(a[2]), "r"(a[3]), "r"(b0), "r"(b1));
}
__device__ __forceinline__ void cp16(uint32_t dst, const void* src) {
    asm volatile("cp.async.cg.shared.global [%0], [%1], 16;" :: "r"(dst), "l"(src));
}
#define CP_COMMIT() asm volatile("cp.async.commit_group;" ::: "memory")
#define CP_WAIT1()  asm volatile("cp.async.wait_group 1;"  ::: "memory")

// ---------------------------------------------------------------------------
// fp16-split GEMM via mma.sync (HMMA), templated on term counts.
// A: [M,K] row-major fp16. B: [K,N] row-major fp16.
// CTA tile 128x128, BK=32, 3 cp.async stages, 8 warps (4m x 2n).
// Epilogue modes:
//   KHo != nullptr : K1 routed projection epilogue (fp32 Y / KH+KL / VH)
//   PEo != nullptr : K2 exp epilogue -> PE=fp16(exp(acc-8)) + row-sum partials
//   else           : plain fp32 C (+bias)
// ---------------------------------------------------------------------------
#define STAGES  3
#define APITCH  40                      // fp16 elems per A smem row (80B)
#define BPITCH  136                     // fp16 elems per B smem row (272B)
#define A_STG   (128 * APITCH * 2)      // 10240 B per term buffer
#define B_STG   (32 * BPITCH * 2)       // 8704 B

template<int AT, int BT>
__global__ void __launch_bounds__(256, (AT == 1) ? 2 : 1) gemm_mma(
    const __half* __restrict__ Ah, const __half* __restrict__ Al,
    const __half* __restrict__ Bh, const __half* __restrict__ Bl,
    const float* __restrict__ bias, float* __restrict__ C,
    int K, int lda, int ldb, int ldc,
    size_t sA, size_t sB, size_t sC, int has_bias,
    __half* __restrict__ KHo, __half* __restrict__ KLo, __half* __restrict__ VHo,
    __half* __restrict__ PEo, float* __restrict__ Part)
{
    constexpr int STG_BYTES = AT * A_STG + BT * B_STG;
    extern __shared__ char smem[];
    __shared__ float sred[2][128];
    const uint32_t sb = smem_to_u32(smem);
    const int tid  = threadIdx.x;
    const int w    = tid >> 5, lane = tid & 31;
    const int wm   = w & 3,    wn   = w >> 2;
    const int b    = blockIdx.z;
    const int m0   = blockIdx.y * 128, n0 = blockIdx.x * 128;

    const __half* Ag[AT];
    Ag[0] = Ah + (size_t)b * sA + (size_t)m0 * lda;
    if (AT == 2) Ag[1] = Al + (size_t)b * sA + (size_t)m0 * lda;
    const __half* Bg[BT];
    Bg[0] = Bh + (size_t)b * sB + n0;
    if (BT == 2) Bg[1] = Bl + (size_t)b * sB + n0;

    const int nk = K >> 5;

    const int a_row = tid >> 2, a_ch = (tid & 3) << 3;     // 64 rows / iter
    const int b_row = tid >> 4, b_ch = (tid & 15) << 3;    // 16 rows / iter

    auto issue = [&](int stage, int kt) {
        const uint32_t base = sb + stage * STG_BYTES;
        const int k0 = kt << 5;
#pragma unroll
        for (int h = 0; h < AT; h++) {
            const __half* asrc = Ag[h] + k0;
            const uint32_t adst = base + h * A_STG;
#pragma unroll
            for (int r = 0; r < 2; r++) {
                int row = a_row + r * 64;
                cp16(adst + (uint32_t)(row * APITCH + a_ch) * 2,
                     asrc + (size_t)row * lda + a_ch);
            }
        }
#pragma unroll
        for (int h = 0; h < BT; h++) {
            const __half* bsrc = Bg[h];
            const uint32_t bdst = base + AT * A_STG + h * B_STG;
#pragma unroll
            for (int r = 0; r < 2; r++) {
                int row = b_row + r * 16;
                cp16(bdst + (uint32_t)(row * BPITCH + b_ch) * 2,
                     bsrc + (size_t)(k0 + row) * ldb + b_ch);
            }
        }
    };

    float c[2][8][4];
#pragma unroll
    for (int mi = 0; mi < 2; mi++)
#pragma unroll
        for (int j = 0; j < 8; j++)
#pragma unroll
            for (int q = 0; q < 4; q++) c[mi][j][q] = 0.0f;

    issue(0, 0); CP_COMMIT();
    if (nk > 1) issue(1, 1);
    CP_COMMIT();

    const uint32_t a_lane_off = (uint32_t)((lane & 15) * APITCH + ((lane >> 4) << 3)) * 2;
    const uint32_t b_lane_off = (uint32_t)((lane & 15) * BPITCH + ((lane >> 4) << 3)) * 2;

    for (int kt = 0; kt < nk; kt++) {
        CP_WAIT1();
        __syncthreads();
        int kf = kt + STAGES - 1;
        if (kf < nk) issue(kf % STAGES, kf);
        CP_COMMIT();

        const int stage = kt % STAGES;
        const uint32_t ab = sb + stage * STG_BYTES;
        const uint32_t bb = ab + AT * A_STG;

#pragma unroll
        for (int ks = 0; ks < 2; ks++) {
            uint32_t afr[AT][2][4];
            uint32_t bfr[BT][4][4];
#pragma unroll
            for (int h = 0; h < AT; h++)
#pragma unroll
                for (int mi = 0; mi < 2; mi++)
                    ldsm4(afr[h][mi],
                          ab + h * A_STG + a_lane_off +
                          (uint32_t)((wm * 32 + mi * 16) * APITCH + ks * 16) * 2);
#pragma unroll
            for (int h = 0; h < BT; h++)
#pragma unroll
                for (int nj = 0; nj < 4; nj++)
                    ldsm4t(bfr[h][nj],
                           bb + h * B_STG + b_lane_off +
                           (uint32_t)(ks * 16 * BPITCH + wn * 64 + nj * 16) * 2);
#pragma unroll
            for (int mi = 0; mi < 2; mi++)
#pragma unroll
                for (int j = 0; j < 8; j++) {
                    const int nj = j >> 1, hf = (j & 1) << 1;
                    mma16816(c[mi][j], afr[0][mi], bfr[0][nj][hf], bfr[0][nj][hf + 1]);
                    if (BT == 2)
                        mma16816(c[mi][j], afr[0][mi], bfr[1][nj][hf], bfr[1][nj][hf + 1]);
                    if (AT == 2)
                        mma16816(c[mi][j], afr[1][mi], bfr[0][nj][hf], bfr[0][nj][hf + 1]);
                }
        }
        __syncthreads();
    }

    // ---- epilogue ----
    const int colbase = n0 + wn * 64 + (lane & 3) * 2;
    if (KHo != nullptr) {
        // routed projection epilogue (K1)
#pragma unroll
        for (int mi = 0; mi < 2; mi++)
#pragma unroll
            for (int rr = 0; rr < 2; rr++) {
                const int row = m0 + wm * 32 + mi * 16 + (lane >> 2) + rr * 8;
                if (row >= MTOT) continue;
                const float bv = bias[row];
                if (row < 64 || row >= 640) {
                    float* p = C + (size_t)b * sC + (size_t)row * ldc + colbase;
#pragma unroll
                    for (int j = 0; j < 8; j++)
                        *reinterpret_cast<float2*>(p + j * 8) =
                            make_float2(c[mi][j][rr * 2] + bv, c[mi][j][rr * 2 + 1] + bv);
                } else if (row < 128) {
                    __half* ph = KHo + ((size_t)b * 64 + (row - 64)) * HW + colbase;
                    __half* pl = KLo + ((size_t)b * 64 + (row - 64)) * HW + colbase;
#pragma unroll
                    for (int j = 0; j < 8; j++) {
                        float v0 = c[mi][j][rr * 2] + bv, v1 = c[mi][j][rr * 2 + 1] + bv;
                        __half h0 = __float2half_rn(v0), h1 = __float2half_rn(v1);
                        *reinterpret_cast<__half2*>(ph + j * 8) = __halves2half2(h0, h1);
                        *reinterpret_cast<__half2*>(pl + j * 8) = __halves2half2(
                            __float2half_rn(v0 - __half2float(h0)),
                            __float2half_rn(v1 - __half2float(h1)));
                    }
                } else {
                    __half* ph = VHo + ((size_t)b * 512 + (row - 128)) * HW + colbase;
#pragma unroll
                    for (int j = 0; j < 8; j++)
                        *reinterpret_cast<__half2*>(ph + j * 8) = __halves2half2(
                            __float2half_rn(c[mi][j][rr * 2] + bv),
                            __float2half_rn(c[mi][j][rr * 2 + 1] + bv));
                }
            }
    } else if (PEo != nullptr) {
        // K2 exp epilogue: PE = fp16(exp(acc - 8)), plus row-sum partials.
#pragma unroll
        for (int mi = 0; mi < 2; mi++)
#pragma unroll
            for (int rr = 0; rr < 2; rr++) {
                const int rloc = wm * 32 + mi * 16 + (lane >> 2) + rr * 8;
                __half* pp = PEo + ((size_t)b * HW + m0 + rloc) * HW + colbase;
                float rsum = 0.0f;
#pragma unroll
                for (int j = 0; j < 8; j++) {
                    float e0 = __expf(c[mi][j][rr * 2]     - 8.0f);
                    float e1 = __expf(c[mi][j][rr * 2 + 1] - 8.0f);
                    __half h0 = __float2half_rn(e0), h1 = __float2half_rn(e1);
                    *reinterpret_cast<__half2*>(pp + j * 8) = __halves2half2(h0, h1);
                    rsum += __half2float(h0) + __half2float(h1);
                }
                rsum += __shfl_xor_sync(0xffffffffu, rsum, 1);
                rsum += __shfl_xor_sync(0xffffffffu, rsum, 2);
                if ((lane & 3) == 0) sred[wn][rloc] = rsum;
            }
        __syncthreads();
        if (tid < 128) {
            float z = sred[0][tid] + sred[1][tid];
            Part[((size_t)b * 32 + blockIdx.x) * HW + m0 + tid] = z;
        }
    } else {
#pragma unroll
        for (int mi = 0; mi < 2; mi++) {
            const int r0 = m0 + wm * 32 + mi * 16 + (lane >> 2);
            const float bv0 = has_bias ? bias[r0]     : 0.0f;
            const float bv1 = has_bias ? bias[r0 + 8] : 0.0f;
            float* p0 = C + (size_t)b * sC + (size_t)r0 * ldc + colbase;
            float* p1 = p0 + (size_t)8 * ldc;
#pragma unroll
            for (int j = 0; j < 8; j++) {
                *reinterpret_cast<float2*>(p0 + j * 8) =
                    make_float2(c[mi][j][0] + bv0, c[mi][j][1] + bv0);
                *reinterpret_cast<float2*>(p1 + j * 8) =
                    make_float2(c[mi][j][2] + bv1, c[mi][j][3] + bv1);
            }
        }
    }
}

// ---------------------------------------------------------------------------
// Z reduction + v column scaling
// ---------------------------------------------------------------------------
__global__ void zinv_k(const float* __restrict__ Part, float* __restrict__ zinv)
{
    int i = blockIdx.x * 256 + threadIdx.x;   // over B*HW
    int b = i >> 12, r = i & 4095;
    float s = 0.0f;
#pragma unroll
    for (int jt = 0; jt < 32; jt++) s += Part[((size_t)b * 32 + jt) * HW + r];
    zinv[i] = 1.0f / s;
}

__global__ void vscale_k(__half* __restrict__ VH, const float* __restrict__ zinv)
{
    const int b = blockIdx.y;
    int idx = blockIdx.x * 256 + threadIdx.x;   // over 512*2048 half2 per batch
    int c  = idx >> 11;
    int i2 = idx & 2047;
    __half2* p = reinterpret_cast<__half2*>(VH + ((size_t)b * 512 + c) * HW) + i2;
    float2 f = __half22float2(*p);
    float z0 = zinv[(size_t)b * HW + 2 * i2];
    float z1 = zinv[(size_t)b * HW + 2 * i2 + 1];
    *p = __floats2half2_rn(f.x * z0, f.y * z1);
}

// ---------------------------------------------------------------------------
// fp16 split conversions
// ---------------------------------------------------------------------------
__global__ void split4(const float* __restrict__ in, __half* __restrict__ hi,
                       __half* __restrict__ lo, int count4,
                       size_t in_bs, size_t out_bs)
{
    size_t b = blockIdx.y;
    int i = blockIdx.x * 256 + threadIdx.x;
    if (i >= count4) return;
    float4 v = reinterpret_cast<const float4*>(in + b * in_bs)[i];
    __half h0 = __float2half_rn(v.x), h1 = __float2half_rn(v.y);
    __half h2 = __float2half_rn(v.z), h3 = __float2half_rn(v.w);
    __half l0 = __float2half_rn(v.x - __half2float(h0));
    __half l1 = __float2half_rn(v.y - __half2float(h1));
    __half l2 = __float2half_rn(v.z - __half2float(h2));
    __half l3 = __float2half_rn(v.w - __half2float(h3));
    __half2* ph = reinterpret_cast<__half2*>(hi + b * out_bs);
    __half2* pl = reinterpret_cast<__half2*>(lo + b * out_bs);
    ph[2 * i]     = __halves2half2(h0, h1);
    ph[2 * i + 1] = __halves2half2(h2, h3);
    pl[2 * i]     = __halves2half2(l0, l1);
    pl[2 * i + 1] = __halves2half2(l2, l3);
}

__global__ void splitW(const float* __restrict__ in, __half* __restrict__ hi,
                       __half* __restrict__ lo)
{
    int i = blockIdx.x * 256 + threadIdx.x;     // 0..896*512-1
    float v = (i < MTOT * CH) ? in[i] : 0.0f;
    __half h = __float2half_rn(v);
    hi[i] = h;
    lo[i] = __float2half_rn(v - __half2float(h));
}

// q [64,HW] per batch (rows 0..63 of Y) -> qT [HW,64] hi/lo
__global__ void qtrans_split(const float* __restrict__ Y, __half* __restrict__ qh,
                             __half* __restrict__ ql)
{
    __shared__ float s[64][65];
    int b = blockIdx.y;
    int i0 = blockIdx.x * 64;
    const float* q = Y + (size_t)b * MPAD * HW;
    for (int u = threadIdx.x; u < 64 * 64; u += 256) {
        int c = u >> 6, i = u & 63;
        s[c][i] = q[(size_t)c * HW + i0 + i];
    }
    __syncthreads();
    for (int u = threadIdx.x; u < 64 * 64; u += 256) {
        int i = u >> 6, c = u & 63;
        float v = s[c][i];
        __half h = __float2half_rn(v);
        size_t o = ((size_t)b * HW + i0 + i) * 64 + c;
        qh[o] = h;
        ql[o] = __float2half_rn(v - __half2float(h));
    }
}

// ---------------------------------------------------------------------------
// SIMT f32x2 GEMM (small K8 accumulate)
// ---------------------------------------------------------------------------
__device__ __forceinline__ unsigned long long pk2(float lo, float hi) {
    unsigned long long r;
    asm("mov.b64 %0, {%1, %2};" : "=l"(r) : "f"(lo), "f"(hi));
    return r;
}
__device__ __forceinline__ unsigned long long fma2(unsigned long long a,
                                                   unsigned long long b,
                                                   unsigned long long c) {
    unsigned long long d;
    asm("fma.rn.f32x2 %0, %1, %2, %3;" : "=l"(d) : "l"(a), "l"(b), "l"(c));
    return d;
}
__device__ __forceinline__ float2 u2f(unsigned long long u) {
    float2 f;
    asm("mov.b64 {%0, %1}, %2;" : "=f"(f.x), "=f"(f.y) : "l"(u));
    return f;
}

__global__ __launch_bounds__(256, 2)
void gemm_acc(const float* __restrict__ A, const float* __restrict__ Bm,
              const float* __restrict__ bias, float* __restrict__ Cm,
              int M, int N, int K, int lda, int ldb, int ldc,
              size_t sA, size_t sB, size_t sC)
{
    __shared__ float As[16][128 + 4];
    __shared__ float Bs[16][128];

    const int b  = blockIdx.z;
    const float* Ab = A + (size_t)b * sA;
    const float* Bb = Bm + (size_t)b * sB;
    float*       Cb = Cm + (size_t)b * sC;

    const int m0 = blockIdx.y * 128;
    const int n0 = blockIdx.x * 128;
    const int t  = threadIdx.x;
    const int tm0 = (t >> 4) << 3;
    const int tn0 = (t & 15) << 3;

    unsigned long long acc[8][4];
#pragma unroll
    for (int i = 0; i < 8; i++)
#pragma unroll
        for (int j = 0; j < 4; j++) acc[i][j] = 0ull;

    for (int k0 = 0; k0 < K; k0 += 16) {
#pragma unroll
        for (int r = 0; r < 2; r++) {
            int idx = t + r * 256;
            int row = idx >> 2;
            int c4  = (idx & 3) << 2;
            float4 v = make_float4(0.f, 0.f, 0.f, 0.f);
            if (m0 + row < M)
                v = *reinterpret_cast<const float4*>(Ab + (size_t)(m0 + row) * lda + k0 + c4);
            As[c4 + 0][row] = v.x; As[c4 + 1][row] = v.y;
            As[c4 + 2][row] = v.z; As[c4 + 3][row] = v.w;
        }
#pragma unroll
        for (int r = 0; r < 2; r++) {
            int idx = t + r * 256;
            int kr  = idx >> 5;
            int n4  = (idx & 31) << 2;
            float4 v = *reinterpret_cast<const float4*>(Bb + (size_t)(k0 + kr) * ldb + n0 + n4);
            *reinterpret_cast<float4*>(&Bs[kr][n4]) = v;
        }
        __syncthreads();
#pragma unroll
        for (int kk = 0; kk < 16; kk++) {
            float4 a0 = *reinterpret_cast<const float4*>(&As[kk][tm0]);
            float4 a1 = *reinterpret_cast<const float4*>(&As[kk][tm0 + 4]);
            ulonglong2 bl0 = *reinterpret_cast<const ulonglong2*>(&Bs[kk][tn0]);
            ulonglong2 bl1 = *reinterpret_cast<const ulonglong2*>(&Bs[kk][tn0 + 4]);
            unsigned long long bv[4] = {bl0.x, bl0.y, bl1.x, bl1.y};
            float av[8] = {a0.x, a0.y, a0.z, a0.w, a1.x, a1.y, a1.z, a1.w};
#pragma unroll
            for (int i = 0; i < 8; i++) {
                unsigned long long a2 = pk2(av[i], av[i]);
#pragma unroll
                for (int j = 0; j < 4; j++) acc[i][j] = fma2(a2, bv[j], acc[i][j]);
            }
        }
        __syncthreads();
    }
#pragma unroll
    for (int i = 0; i < 8; i++) {
        int m = m0 + tm0 + i;
        if (m >= M) continue;
        float bsv = bias[m];
        float* crow = Cb + (size_t)m * ldc + n0 + tn0;
#pragma unroll
        for (int j = 0; j < 4; j++) {
            float2 f = u2f(acc[i][j]);
            float2 o = *reinterpret_cast<const float2*>(crow + j * 2);
            f.x += bsv + o.x; f.y += bsv + o.y;
            *reinterpret_cast<float2*>(crow + j * 2) = f;
        }
    }
}

// ---------------------------------------------------------------------------
// Channel attention kernels (fp32, small)
// ---------------------------------------------------------------------------
__global__ void chan_energy(const float* __restrict__ cq, const float* __restrict__ ck,
                            float* __restrict__ part)
{
    __shared__ float sq[64][65];
    __shared__ float sk[64][65];
    const int b = blockIdx.y;
    const int split = blockIdx.x;
    const float* cqb = cq + (size_t)b * MPAD * HW;
    const float* ckb = ck + (size_t)b * MPAD * HW;
    const int t = threadIdx.x;
    const int p0 = (t >> 4) * 4;
    const int q0 = (t & 15) * 4;

    float acc[4][4];
#pragma unroll
    for (int i = 0; i < 4; i++)
#pragma unroll
        for (int j = 0; j < 4; j++) acc[i][j] = 0.f;

    for (int c = 0; c < 4; c++) {
        const int nb = (split * 4 + c) * 64;
        __syncthreads();
#pragma unroll
        for (int i = 0; i < 16; i++) {
            int idx = t + i * 256;
            int row = idx >> 6, col = idx & 63;
            sq[row][col] = cqb[(size_t)row * HW + nb + col];
            sk[row][col] = ckb[(size_t)row * HW + nb + col];
        }
        __syncthreads();
        for (int nn = 0; nn < 64; nn++) {
            float aq[4], bk[4];
#pragma unroll
            for (int i = 0; i < 4; i++) aq[i] = sq[p0 + i][nn];
#pragma unroll
            for (int j = 0; j < 4; j++) bk[j] = sk[q0 + j][nn];
#pragma unroll
            for (int i = 0; i < 4; i++)
#pragma unroll
                for (int j = 0; j < 4; j++) acc[i][j] += aq[i] * bk[j];
        }
    }
    float* out = part + (size_t)split * (BATCH * 4096) + (size_t)b * 4096;
#pragma unroll
    for (int i = 0; i < 4; i++)
#pragma unroll
        for (int j = 0; j < 4; j++)
            out[(p0 + i) * 64 + (q0 + j)] = acc[i][j];
}

__global__ void reduce_ce(const float* __restrict__ part, float* __restrict__ cE)
{
    int i = blockIdx.x * 256 + threadIdx.x;
    float s = 0.f;
#pragma unroll
    for (int k = 0; k < 16; k++) s += part[(size_t)k * (BATCH * 4096) + i];
    cE[i] = s;
}

__global__ void chan_softmax(float* __restrict__ cE)
{
    __shared__ float red[64];
    const int row = blockIdx.x;
    float* rp = cE + (size_t)row * 64;
    const int t = threadIdx.x;
    float v = rp[t];
    red[t] = v; __syncthreads();
    for (int s = 32; s > 0; s >>= 1) {
        if (t < s) red[t] = fmaxf(red[t], red[t + s]);
        __syncthreads();
    }
    float m = red[0]; __syncthreads();
    float e = __expf(v - m);
    red[t] = e; __syncthreads();
    for (int s = 32; s > 0; s >>= 1) {
        if (t < s) red[t] += red[t + s];
        __syncthreads();
    }
    rp[t] = e / red[0];
}

__global__ void chan_out(const float* __restrict__ cattn, const float* __restrict__ cv,
                         float* __restrict__ cout)
{
    __shared__ float sa[4096];
    const int b = blockIdx.y;
    const int n = blockIdx.x * 256 + threadIdx.x;
    const float* at = cattn + (size_t)b * 4096;
    for (int i = threadIdx.x; i < 4096; i += 256) sa[i] = at[i];
    __syncthreads();

    const float* cvb = cv + (size_t)b * MPAD * HW;
    float acc[64];
#pragma unroll
    for (int p = 0; p < 64; p++) acc[p] = 0.f;
    for (int q = 0; q < 64; q++) {
        float vv = cvb[(size_t)q * HW + n];
#pragma unroll
        for (int p = 0; p < 64; p++) acc[p] += sa[p * 64 + q] * vv;
    }
    float* ob = cout + (size_t)b * CQD * HW;
#pragma unroll
    for (int p = 0; p < 64; p++) ob[(size_t)p * HW + n] = acc[p];
}

// ---------------------------------------------------------------------------
// Launch
// ---------------------------------------------------------------------------
extern "C" void kernel_launch(void* const* d_in, const int* in_sizes, int n_in,
                              void* d_out, int out_size)
{
    (void)in_sizes; (void)n_in; (void)out_size;

    const float* x = (const float*)d_in[0];

    float* S = nullptr;
    cudaGetSymbolAddress((void**)&S, g_scratch);

    float* W    = S + OFF_W;
    float* BI   = S + OFF_BI;
    float* Y    = S + OFF_Y;
    float* PART = S + OFF_PART;
    float* ZINV = S + OFF_ZINV;
    float* CE   = S + OFF_CE;
    float* CEP  = S + OFF_CEP;
    float* CO   = S + OFF_CO;
    float* out  = (float*)d_out;

    __half* WH  = (__half*)(S + OFF_WH);
    __half* WL  = (__half*)(S + OFF_WL);
    __half* XH  = (__half*)(S + OFF_XH);
    __half* XL  = (__half*)(S + OFF_XL);
    __half* QTH = (__half*)(S + OFF_QTH);
    __half* QTL = (__half*)(S + OFF_QTL);
    __half* KH  = (__half*)(S + OFF_KH);
    __half* KL  = (__half*)(S + OFF_KL);
    __half* VH  = (__half*)(S + OFF_VH);
    __half* PH  = (__half*)(S + OFF_PH);

    // pack fp32 weights + bias
    cudaMemcpyAsync(W +      0, d_in[1],  64  * 512 * sizeof(float), cudaMemcpyDeviceToDevice);
    cudaMemcpyAsync(W +  32768, d_in[3],  64  * 512 * sizeof(float), cudaMemcpyDeviceToDevice);
    cudaMemcpyAsync(W +  65536, d_in[5],  512 * 512 * sizeof(float), cudaMemcpyDeviceToDevice);
    cudaMemcpyAsync(W + 327680, d_in[7],  64  * 512 * sizeof(float), cudaMemcpyDeviceToDevice);
    cudaMemcpyAsync(W + 360448, d_in[9],  64  * 512 * sizeof(float), cudaMemcpyDeviceToDevice);
    cudaMemcpyAsync(W + 393216, d_in[11], 64  * 512 * sizeof(float), cudaMemcpyDeviceToDevice);
    cudaMemcpyAsync(BI +   0, d_in[2],  64  * sizeof(float), cudaMemcpyDeviceToDevice);
    cudaMemcpyAsync(BI +  64, d_in[4],  64  * sizeof(float), cudaMemcpyDeviceToDevice);
    cudaMemcpyAsync(BI + 128, d_in[6],  512 * sizeof(float), cudaMemcpyDeviceToDevice);
    cudaMemcpyAsync(BI + 640, d_in[8],  64  * sizeof(float), cudaMemcpyDeviceToDevice);
    cudaMemcpyAsync(BI + 704, d_in[10], 64  * sizeof(float), cudaMemcpyDeviceToDevice);
    cudaMemcpyAsync(BI + 768, d_in[12], 64  * sizeof(float), cudaMemcpyDeviceToDevice);

    const int SM22 = STAGES * (2 * A_STG + 2 * B_STG);   // 113664
    const int SM11 = STAGES * (1 * A_STG + 1 * B_STG);   // 56832
    cudaFuncSetAttribute(gemm_mma<2, 2>, cudaFuncAttributeMaxDynamicSharedMemorySize, SM22);
    cudaFuncSetAttribute(gemm_mma<1, 1>, cudaFuncAttributeMaxDynamicSharedMemorySize, SM11);

    // fp16 splits of W and x
    splitW<<<(MPAD * CH + 255) / 256, 256>>>(W, WH, WL);
    split4<<<dim3(2048, BATCH), 256>>>(x, XH, XL, 524288, (size_t)CH * HW, (size_t)CH * HW);

    // K1: projections, routed epilogue -> Y fp32 (q+channel rows), KH/KL, VH
    gemm_mma<2, 2><<<dim3(32, 7, BATCH), 256, SM22>>>(
        WH, WL, XH, XL, BI, Y, 512, 512, HW, HW,
        (size_t)0, (size_t)CH * HW, (size_t)MPAD * HW, 1, KH, KL, VH,
        nullptr, nullptr);

    // q (rows 0..63 of Y) transpose + split
    qtrans_split<<<dim3(64, BATCH), 256>>>(Y, QTH, QTL);

    // K2: energy + fused exp -> PE fp16 + row-sum partials  (3-term)
    gemm_mma<2, 2><<<dim3(32, 32, BATCH), 256, SM22>>>(
        QTH, QTL, KH, KL, nullptr, nullptr, 64, 64, HW, 0,
        (size_t)HW * 64, (size_t)64 * HW, (size_t)0, 0,
        nullptr, nullptr, nullptr, PH, PART);

    // Z reduction + fold 1/Z into v columns
    zinv_k<<<BATCH * HW / 256, 256>>>(PART, ZINV);
    vscale_k<<<dim3(4096, BATCH), 256>>>(VH, ZINV);

    // K4: pos_out = vscaled @ PE   M=512 N=4096 K=4096  (single-term fp16)
    gemm_mma<1, 1><<<dim3(32, 4, BATCH), 256, SM11>>>(
        VH, nullptr, PH, nullptr, nullptr, out, HW, HW, HW, HW,
        (size_t)CH * HW, (size_t)HW * HW, (size_t)CH * HW, 0,
        nullptr, nullptr, nullptr, nullptr, nullptr);

    // Channel path (fp32, Y rows 640/704/768)
    chan_energy<<<dim3(16, BATCH), 256>>>(Y + (size_t)640 * HW, Y + (size_t)704 * HW, CEP);
    reduce_ce<<<128, 256>>>(CEP, CE);
    chan_softmax<<<BATCH * 64, 64>>>(CE);
    chan_out<<<dim3(16, BATCH), 256>>>(CE, Y + (size_t)768 * HW, CO);

    // K8: d_out += co_w @ c_out + co_b   M=512 N=4096 K=64 (SIMT)
    gemm_acc<<<dim3(32, 4, BATCH), 256>>>(
        (const float*)d_in[13], CO, (const float*)d_in[14], out,
        CH, HW, CQD, CQD, HW, HW,
        (size_t)0, (size_t)CQD * HW, (size_t)CH * HW);
}

// round 7
// speedup vs baseline: 4.5793x; 1.2568x over previous
#include <cuda_runtime.h>
#include <cuda_fp16.h>
#include <cstdint>
#include <cstddef>

// ---------------------------------------------------------------------------
// Problem constants
// ---------------------------------------------------------------------------
#define BATCH 8
#define CH    512
#define CQD   64
#define HW    4096
#define MTOT  832          // packed projection rows (pq,pk,pv,cq,ck,cv)
#define MPAD  896          // padded to multiple of 128

// scratch layout (float offsets)
#define OFF_W    0u            // packed fp32 weights [832,512]
#define OFF_BI   425984u       // packed bias
#define OFF_WH   427008u       // W hi fp16 [896,512]
#define OFF_WL   656384u       // W lo fp16
#define OFF_XH   885760u       // x fp16 [8,512,4096]
#define OFF_Y    17662976u     // fp32 projections [8,896,4096] (q + channel rows)
#define OFF_QTH  47023104u     // qT fp16 [8,4096,64]
#define OFF_KH   49120256u     // k fp16 [8,64,4096]
#define OFF_VH   51217408u     // v fp16 [8,512,4096] (later scaled by 1/Z)
#define OFF_PH   59606016u     // PE = exp(E-8) fp16 [8,4096,4096]
#define OFF_PART 126714880u    // row-sum partials fp32 [8,32,4096]
#define OFF_ZINV 127763456u    // 1/Z fp32 [8,4096]
#define OFF_CE   127796224u
#define OFF_CEP  127828992u
#define OFF_CO   128353280u
#define SCRATCH_FLOATS 130450432u

__device__ float g_scratch[SCRATCH_FLOATS];

// ---------------------------------------------------------------------------
// PTX helpers (base-ISA only: mma.sync / ldmatrix / cp.async)
// ---------------------------------------------------------------------------
__device__ __forceinline__ uint32_t smem_to_u32(const void* p) {
    uint32_t a;
    asm("{ .reg .u64 t; cvta.to.shared.u64 t, %1; cvt.u32.u64 %0, t; }" : "=r"(a) : "l"(p));
    return a;
}

__device__ __forceinline__ void ldsm4(uint32_t* r, uint32_t addr) {
    asm volatile("ldmatrix.sync.aligned.m8n8.x4.shared.b16 {%0,%1,%2,%3}, [%4];"
                 : "=r"(r[0]), "=r"(r[1]), "=r"(r[2]), "=r"(r[3]) : "r"(addr));
}
__device__ __forceinline__ void ldsm4t(uint32_t* r, uint32_t addr) {
    asm volatile("ldmatrix.sync.aligned.m8n8.x4.trans.shared.b16 {%0,%1,%2,%3}, [%4];"
                 : "=r"(r[0]), "=r"(r[1]), "=r"(r[2]), "=r"(r[3]) : "r"(addr));
}
__device__ __forceinline__ void mma16816(float* c, const uint32_t* a,
                                         uint32_t b0, uint32_t b1) {
    asm volatile("mma.sync.aligned.m16n8k16.row.col.f32.f16.f16.f32 "
                 "{%0,%1,%2,%3}, {%4,%5,%6,%7}, {%8,%9}, {%0,%1,%2,%3};"
                 : "+f"(c[0]), "+f"(c[1]), "+f"(c[2]), "+f"(c[3])
                 : "r"(a[0]), "r"(a[1]), "r"(a[2]), "r"(a[3]), "r"(b0), "r"(b1));
}
__device__ __forceinline__ void cp16(uint32_t dst, const void* src) {
    asm volatile("cp.async.cg.shared.global [%0], [%1], 16;" :: "r"(dst), "l"(src));
}
#define CP_COMMIT() asm volatile("cp.async.commit_group;" ::: "memory")
#define CP_WAIT1()  asm volatile("cp.async.wait_group 1;"  ::: "memory")

// ---------------------------------------------------------------------------
// fp16-split GEMM via mma.sync (HMMA), templated on term counts.
//   AT=2,BT=1: C = Ah@B + Al@B     AT=1,BT=1: C = A@B
// A: [M,K] row-major fp16. B: [K,N] row-major fp16.
// CTA tile 128x128, BK=32, 3 cp.async stages, 8 warps (4m x 2n), 2 CTAs/SM.
// Epilogue modes:
//   KHo != nullptr : K1 routed projection epilogue (fp32 Y / KH / VH)
//   PEo != nullptr : K2 exp epilogue -> PE=fp16(exp(acc-8)) + row-sum partials
//   else           : plain fp32 C (+bias)
// ---------------------------------------------------------------------------
#define STAGES  3
#define APITCH  40                      // fp16 elems per A smem row (80B)
#define BPITCH  136                     // fp16 elems per B smem row (272B)
#define A_STG   (128 * APITCH * 2)      // 10240 B per term buffer
#define B_STG   (32 * BPITCH * 2)       // 8704 B

template<int AT, int BT>
__global__ void __launch_bounds__(256, 2) gemm_mma(
    const __half* __restrict__ Ah, const __half* __restrict__ Al,
    const __half* __restrict__ Bh,
    const float* __restrict__ bias, float* __restrict__ C,
    int K, int lda, int ldb, int ldc,
    size_t sA, size_t sB, size_t sC, int has_bias,
    __half* __restrict__ KHo, __half* __restrict__ VHo,
    __half* __restrict__ PEo, float* __restrict__ Part)
{
    constexpr int STG_BYTES = AT * A_STG + BT * B_STG;
    extern __shared__ char smem[];
    __shared__ float sred[2][128];
    const uint32_t sb = smem_to_u32(smem);
    const int tid  = threadIdx.x;
    const int w    = tid >> 5, lane = tid & 31;
    const int wm   = w & 3,    wn   = w >> 2;
    const int b    = blockIdx.z;
    const int m0   = blockIdx.y * 128, n0 = blockIdx.x * 128;

    const __half* Ag[AT];
    Ag[0] = Ah + (size_t)b * sA + (size_t)m0 * lda;
    if (AT == 2) Ag[1] = Al + (size_t)b * sA + (size_t)m0 * lda;
    const __half* Bg0 = Bh + (size_t)b * sB + n0;

    const int nk = K >> 5;

    const int a_row = tid >> 2, a_ch = (tid & 3) << 3;     // 64 rows / iter
    const int b_row = tid >> 4, b_ch = (tid & 15) << 3;    // 16 rows / iter

    auto issue = [&](int stage, int kt) {
        const uint32_t base = sb + stage * STG_BYTES;
        const int k0 = kt << 5;
#pragma unroll
        for (int h = 0; h < AT; h++) {
            const __half* asrc = Ag[h] + k0;
            const uint32_t adst = base + h * A_STG;
#pragma unroll
            for (int r = 0; r < 2; r++) {
                int row = a_row + r * 64;
                cp16(adst + (uint32_t)(row * APITCH + a_ch) * 2,
                     asrc + (size_t)row * lda + a_ch);
            }
        }
        {
            const uint32_t bdst = base + AT * A_STG;
#pragma unroll
            for (int r = 0; r < 2; r++) {
                int row = b_row + r * 16;
                cp16(bdst + (uint32_t)(row * BPITCH + b_ch) * 2,
                     Bg0 + (size_t)(k0 + row) * ldb + b_ch);
            }
        }
    };

    float c[2][8][4];
#pragma unroll
    for (int mi = 0; mi < 2; mi++)
#pragma unroll
        for (int j = 0; j < 8; j++)
#pragma unroll
            for (int q = 0; q < 4; q++) c[mi][j][q] = 0.0f;

    issue(0, 0); CP_COMMIT();
    if (nk > 1) issue(1, 1);
    CP_COMMIT();

    const uint32_t a_lane_off = (uint32_t)((lane & 15) * APITCH + ((lane >> 4) << 3)) * 2;
    const uint32_t b_lane_off = (uint32_t)((lane & 15) * BPITCH + ((lane >> 4) << 3)) * 2;

    for (int kt = 0; kt < nk; kt++) {
        CP_WAIT1();
        __syncthreads();
        int kf = kt + STAGES - 1;
        if (kf < nk) issue(kf % STAGES, kf);
        CP_COMMIT();

        const int stage = kt % STAGES;
        const uint32_t ab = sb + stage * STG_BYTES;
        const uint32_t bb = ab + AT * A_STG;

#pragma unroll
        for (int ks = 0; ks < 2; ks++) {
            uint32_t afr[AT][2][4];
            uint32_t bfr[4][4];
#pragma unroll
            for (int h = 0; h < AT; h++)
#pragma unroll
                for (int mi = 0; mi < 2; mi++)
                    ldsm4(afr[h][mi],
                          ab + h * A_STG + a_lane_off +
                          (uint32_t)((wm * 32 + mi * 16) * APITCH + ks * 16) * 2);
#pragma unroll
            for (int nj = 0; nj < 4; nj++)
                ldsm4t(bfr[nj],
                       bb + b_lane_off +
                       (uint32_t)(ks * 16 * BPITCH + wn * 64 + nj * 16) * 2);
#pragma unroll
            for (int mi = 0; mi < 2; mi++)
#pragma unroll
                for (int j = 0; j < 8; j++) {
                    const int nj = j >> 1, hf = (j & 1) << 1;
                    mma16816(c[mi][j], afr[0][mi], bfr[nj][hf], bfr[nj][hf + 1]);
                    if (AT == 2)
                        mma16816(c[mi][j], afr[1][mi], bfr[nj][hf], bfr[nj][hf + 1]);
                }
        }
        __syncthreads();
    }

    // ---- epilogue ----
    const int colbase = n0 + wn * 64 + (lane & 3) * 2;
    if (KHo != nullptr) {
        // routed projection epilogue (K1)
#pragma unroll
        for (int mi = 0; mi < 2; mi++)
#pragma unroll
            for (int rr = 0; rr < 2; rr++) {
                const int row = m0 + wm * 32 + mi * 16 + (lane >> 2) + rr * 8;
                if (row >= MTOT) continue;
                const float bv = bias[row];
                if (row < 64 || row >= 640) {
                    float* p = C + (size_t)b * sC + (size_t)row * ldc + colbase;
#pragma unroll
                    for (int j = 0; j < 8; j++)
                        *reinterpret_cast<float2*>(p + j * 8) =
                            make_float2(c[mi][j][rr * 2] + bv, c[mi][j][rr * 2 + 1] + bv);
                } else if (row < 128) {
                    __half* ph = KHo + ((size_t)b * 64 + (row - 64)) * HW + colbase;
#pragma unroll
                    for (int j = 0; j < 8; j++)
                        *reinterpret_cast<__half2*>(ph + j * 8) = __halves2half2(
                            __float2half_rn(c[mi][j][rr * 2] + bv),
                            __float2half_rn(c[mi][j][rr * 2 + 1] + bv));
                } else {
                    __half* ph = VHo + ((size_t)b * 512 + (row - 128)) * HW + colbase;
#pragma unroll
                    for (int j = 0; j < 8; j++)
                        *reinterpret_cast<__half2*>(ph + j * 8) = __halves2half2(
                            __float2half_rn(c[mi][j][rr * 2] + bv),
                            __float2half_rn(c[mi][j][rr * 2 + 1] + bv));
                }
            }
    } else if (PEo != nullptr) {
        // K2 exp epilogue: PE = fp16(exp(acc - 8)), plus row-sum partials.
#pragma unroll
        for (int mi = 0; mi < 2; mi++)
#pragma unroll
            for (int rr = 0; rr < 2; rr++) {
                const int rloc = wm * 32 + mi * 16 + (lane >> 2) + rr * 8;
                __half* pp = PEo + ((size_t)b * HW + m0 + rloc) * HW + colbase;
                float rsum = 0.0f;
#pragma unroll
                for (int j = 0; j < 8; j++) {
                    float e0 = __expf(c[mi][j][rr * 2]     - 8.0f);
                    float e1 = __expf(c[mi][j][rr * 2 + 1] - 8.0f);
                    __half h0 = __float2half_rn(e0), h1 = __float2half_rn(e1);
                    *reinterpret_cast<__half2*>(pp + j * 8) = __halves2half2(h0, h1);
                    rsum += __half2float(h0) + __half2float(h1);
                }
                rsum += __shfl_xor_sync(0xffffffffu, rsum, 1);
                rsum += __shfl_xor_sync(0xffffffffu, rsum, 2);
                if ((lane & 3) == 0) sred[wn][rloc] = rsum;
            }
        __syncthreads();
        if (tid < 128) {
            float z = sred[0][tid] + sred[1][tid];
            Part[((size_t)b * 32 + blockIdx.x) * HW + m0 + tid] = z;
        }
    } else {
#pragma unroll
        for (int mi = 0; mi < 2; mi++) {
            const int r0 = m0 + wm * 32 + mi * 16 + (lane >> 2);
            const float bv0 = has_bias ? bias[r0]     : 0.0f;
            const float bv1 = has_bias ? bias[r0 + 8] : 0.0f;
            float* p0 = C + (size_t)b * sC + (size_t)r0 * ldc + colbase;
            float* p1 = p0 + (size_t)8 * ldc;
#pragma unroll
            for (int j = 0; j < 8; j++) {
                *reinterpret_cast<float2*>(p0 + j * 8) =
                    make_float2(c[mi][j][0] + bv0, c[mi][j][1] + bv0);
                *reinterpret_cast<float2*>(p1 + j * 8) =
                    make_float2(c[mi][j][2] + bv1, c[mi][j][3] + bv1);
            }
        }
    }
}

// ---------------------------------------------------------------------------
// Z reduction + v column scaling
// ---------------------------------------------------------------------------
__global__ void zinv_k(const float* __restrict__ Part, float* __restrict__ zinv)
{
    int i = blockIdx.x * 256 + threadIdx.x;   // over B*HW
    int b = i >> 12, r = i & 4095;
    float s = 0.0f;
#pragma unroll
    for (int jt = 0; jt < 32; jt++) s += Part[((size_t)b * 32 + jt) * HW + r];
    zinv[i] = 1.0f / s;
}

__global__ void vscale_k(__half* __restrict__ VH, const float* __restrict__ zinv)
{
    const int b = blockIdx.y;
    int idx = blockIdx.x * 256 + threadIdx.x;   // over 512*2048 half2 per batch
    int c  = idx >> 11;
    int i2 = idx & 2047;
    __half2* p = reinterpret_cast<__half2*>(VH + ((size_t)b * 512 + c) * HW) + i2;
    float2 f = __half22float2(*p);
    float z0 = zinv[(size_t)b * HW + 2 * i2];
    float z1 = zinv[(size_t)b * HW + 2 * i2 + 1];
    *p = __floats2half2_rn(f.x * z0, f.y * z1);
}

// ---------------------------------------------------------------------------
// fp16 conversions
// ---------------------------------------------------------------------------
__global__ void tohalf4(const float* __restrict__ in, __half* __restrict__ hi,
                        int count4, size_t in_bs, size_t out_bs)
{
    size_t b = blockIdx.y;
    int i = blockIdx.x * 256 + threadIdx.x;
    if (i >= count4) return;
    float4 v = reinterpret_cast<const float4*>(in + b * in_bs)[i];
    __half2* ph = reinterpret_cast<__half2*>(hi + b * out_bs);
    ph[2 * i]     = __floats2half2_rn(v.x, v.y);
    ph[2 * i + 1] = __floats2half2_rn(v.z, v.w);
}

__global__ void splitW(const float* __restrict__ in, __half* __restrict__ hi,
                       __half* __restrict__ lo)
{
    int i = blockIdx.x * 256 + threadIdx.x;     // 0..896*512-1
    float v = (i < MTOT * CH) ? in[i] : 0.0f;
    __half h = __float2half_rn(v);
    hi[i] = h;
    lo[i] = __float2half_rn(v - __half2float(h));
}

// q [64,HW] per batch (rows 0..63 of Y) -> qT [HW,64] fp16
__global__ void qtrans_h(const float* __restrict__ Y, __half* __restrict__ qh)
{
    __shared__ float s[64][65];
    int b = blockIdx.y;
    int i0 = blockIdx.x * 64;
    const float* q = Y + (size_t)b * MPAD * HW;
    for (int u = threadIdx.x; u < 64 * 64; u += 256) {
        int c = u >> 6, i = u & 63;
        s[c][i] = q[(size_t)c * HW + i0 + i];
    }
    __syncthreads();
    for (int u = threadIdx.x; u < 64 * 64; u += 256) {
        int i = u >> 6, c = u & 63;
        qh[((size_t)b * HW + i0 + i) * 64 + c] = __float2half_rn(s[c][i]);
    }
}

// ---------------------------------------------------------------------------
// SIMT f32x2 GEMM (small K8 accumulate)
// ---------------------------------------------------------------------------
__device__ __forceinline__ unsigned long long pk2(float lo, float hi) {
    unsigned long long r;
    asm("mov.b64 %0, {%1, %2};" : "=l"(r) : "f"(lo), "f"(hi));
    return r;
}
__device__ __forceinline__ unsigned long long fma2(unsigned long long a,
                                                   unsigned long long b,
                                                   unsigned long long c) {
    unsigned long long d;
    asm("fma.rn.f32x2 %0, %1, %2, %3;" : "=l"(d) : "l"(a), "l"(b), "l"(c));
    return d;
}
__device__ __forceinline__ float2 u2f(unsigned long long u) {
    float2 f;
    asm("mov.b64 {%0, %1}, %2;" : "=f"(f.x), "=f"(f.y) : "l"(u));
    return f;
}

__global__ __launch_bounds__(256, 2)
void gemm_acc(const float* __restrict__ A, const float* __restrict__ Bm,
              const float* __restrict__ bias, float* __restrict__ Cm,
              int M, int N, int K, int lda, int ldb, int ldc,
              size_t sA, size_t sB, size_t sC)
{
    __shared__ float As[16][128 + 4];
    __shared__ float Bs[16][128];

    const int b  = blockIdx.z;
    const float* Ab = A + (size_t)b * sA;
    const float* Bb = Bm + (size_t)b * sB;
    float*       Cb = Cm + (size_t)b * sC;

    const int m0 = blockIdx.y * 128;
    const int n0 = blockIdx.x * 128;
    const int t  = threadIdx.x;
    const int tm0 = (t >> 4) << 3;
    const int tn0 = (t & 15) << 3;

    unsigned long long acc[8][4];
#pragma unroll
    for (int i = 0; i < 8; i++)
#pragma unroll
        for (int j = 0; j < 4; j++) acc[i][j] = 0ull;

    for (int k0 = 0; k0 < K; k0 += 16) {
#pragma unroll
        for (int r = 0; r < 2; r++) {
            int idx = t + r * 256;
            int row = idx >> 2;
            int c4  = (idx & 3) << 2;
            float4 v = make_float4(0.f, 0.f, 0.f, 0.f);
            if (m0 + row < M)
                v = *reinterpret_cast<const float4*>(Ab + (size_t)(m0 + row) * lda + k0 + c4);
            As[c4 + 0][row] = v.x; As[c4 + 1][row] = v.y;
            As[c4 + 2][row] = v.z; As[c4 + 3][row] = v.w;
        }
#pragma unroll
        for (int r = 0; r < 2; r++) {
            int idx = t + r * 256;
            int kr  = idx >> 5;
            int n4  = (idx & 31) << 2;
            float4 v = *reinterpret_cast<const float4*>(Bb + (size_t)(k0 + kr) * ldb + n0 + n4);
            *reinterpret_cast<float4*>(&Bs[kr][n4]) = v;
        }
        __syncthreads();
#pragma unroll
        for (int kk = 0; kk < 16; kk++) {
            float4 a0 = *reinterpret_cast<const float4*>(&As[kk][tm0]);
            float4 a1 = *reinterpret_cast<const float4*>(&As[kk][tm0 + 4]);
            ulonglong2 bl0 = *reinterpret_cast<const ulonglong2*>(&Bs[kk][tn0]);
            ulonglong2 bl1 = *reinterpret_cast<const ulonglong2*>(&Bs[kk][tn0 + 4]);
            unsigned long long bv[4] = {bl0.x, bl0.y, bl1.x, bl1.y};
            float av[8] = {a0.x, a0.y, a0.z, a0.w, a1.x, a1.y, a1.z, a1.w};
#pragma unroll
            for (int i = 0; i < 8; i++) {
                unsigned long long a2 = pk2(av[i], av[i]);
#pragma unroll
                for (int j = 0; j < 4; j++) acc[i][j] = fma2(a2, bv[j], acc[i][j]);
            }
        }
        __syncthreads();
    }
#pragma unroll
    for (int i = 0; i < 8; i++) {
        int m = m0 + tm0 + i;
        if (m >= M) continue;
        float bsv = bias[m];
        float* crow = Cb + (size_t)m * ldc + n0 + tn0;
#pragma unroll
        for (int j = 0; j < 4; j++) {
            float2 f = u2f(acc[i][j]);
            float2 o = *reinterpret_cast<const float2*>(crow + j * 2);
            f.x += bsv + o.x; f.y += bsv + o.y;
            *reinterpret_cast<float2*>(crow + j * 2) = f;
        }
    }
}

// ---------------------------------------------------------------------------
// Channel attention kernels (fp32, small)
// ---------------------------------------------------------------------------
__global__ void chan_energy(const float* __restrict__ cq, const float* __restrict__ ck,
                            float* __restrict__ part)
{
    __shared__ float sq[64][65];
    __shared__ float sk[64][65];
    const int b = blockIdx.y;
    const int split = blockIdx.x;
    const float* cqb = cq + (size_t)b * MPAD * HW;
    const float* ckb = ck + (size_t)b * MPAD * HW;
    const int t = threadIdx.x;
    const int p0 = (t >> 4) * 4;
    const int q0 = (t & 15) * 4;

    float acc[4][4];
#pragma unroll
    for (int i = 0; i < 4; i++)
#pragma unroll
        for (int j = 0; j < 4; j++) acc[i][j] = 0.f;

    for (int c = 0; c < 4; c++) {
        const int nb = (split * 4 + c) * 64;
        __syncthreads();
#pragma unroll
        for (int i = 0; i < 16; i++) {
            int idx = t + i * 256;
            int row = idx >> 6, col = idx & 63;
            sq[row][col] = cqb[(size_t)row * HW + nb + col];
            sk[row][col] = ckb[(size_t)row * HW + nb + col];
        }
        __syncthreads();
        for (int nn = 0; nn < 64; nn++) {
            float aq[4], bk[4];
#pragma unroll
            for (int i = 0; i < 4; i++) aq[i] = sq[p0 + i][nn];
#pragma unroll
            for (int j = 0; j < 4; j++) bk[j] = sk[q0 + j][nn];
#pragma unroll
            for (int i = 0; i < 4; i++)
#pragma unroll
                for (int j = 0; j < 4; j++) acc[i][j] += aq[i] * bk[j];
        }
    }
    float* out = part + (size_t)split * (BATCH * 4096) + (size_t)b * 4096;
#pragma unroll
    for (int i = 0; i < 4; i++)
#pragma unroll
        for (int j = 0; j < 4; j++)
            out[(p0 + i) * 64 + (q0 + j)] = acc[i][j];
}

__global__ void reduce_ce(const float* __restrict__ part, float* __restrict__ cE)
{
    int i = blockIdx.x * 256 + threadIdx.x;
    float s = 0.f;
#pragma unroll
    for (int k = 0; k < 16; k++) s += part[(size_t)k * (BATCH * 4096) + i];
    cE[i] = s;
}

__global__ void chan_softmax(float* __restrict__ cE)
{
    __shared__ float red[64];
    const int row = blockIdx.x;
    float* rp = cE + (size_t)row * 64;
    const int t = threadIdx.x;
    float v = rp[t];
    red[t] = v; __syncthreads();
    for (int s = 32; s > 0; s >>= 1) {
        if (t < s) red[t] = fmaxf(red[t], red[t + s]);
        __syncthreads();
    }
    float m = red[0]; __syncthreads();
    float e = __expf(v - m);
    red[t] = e; __syncthreads();
    for (int s = 32; s > 0; s >>= 1) {
        if (t < s) red[t] += red[t + s];
        __syncthreads();
    }
    rp[t] = e / red[0];
}

__global__ void chan_out(const float* __restrict__ cattn, const float* __restrict__ cv,
                         float* __restrict__ cout)
{
    __shared__ float sa[4096];
    const int b = blockIdx.y;
    const int n = blockIdx.x * 256 + threadIdx.x;
    const float* at = cattn + (size_t)b * 4096;
    for (int i = threadIdx.x; i < 4096; i += 256) sa[i] = at[i];
    __syncthreads();

    const float* cvb = cv + (size_t)b * MPAD * HW;
    float acc[64];
#pragma unroll
    for (int p = 0; p < 64; p++) acc[p] = 0.f;
    for (int q = 0; q < 64; q++) {
        float vv = cvb[(size_t)q * HW + n];
#pragma unroll
        for (int p = 0; p < 64; p++) acc[p] += sa[p * 64 + q] * vv;
    }
    float* ob = cout + (size_t)b * CQD * HW;
#pragma unroll
    for (int p = 0; p < 64; p++) ob[(size_t)p * HW + n] = acc[p];
}

// ---------------------------------------------------------------------------
// Launch
// ---------------------------------------------------------------------------
extern "C" void kernel_launch(void* const* d_in, const int* in_sizes, int n_in,
                              void* d_out, int out_size)
{
    (void)in_sizes; (void)n_in; (void)out_size;

    const float* x = (const float*)d_in[0];

    float* S = nullptr;
    cudaGetSymbolAddress((void**)&S, g_scratch);

    float* W    = S + OFF_W;
    float* BI   = S + OFF_BI;
    float* Y    = S + OFF_Y;
    float* PART = S + OFF_PART;
    float* ZINV = S + OFF_ZINV;
    float* CE   = S + OFF_CE;
    float* CEP  = S + OFF_CEP;
    float* CO   = S + OFF_CO;
    float* out  = (float*)d_out;

    __half* WH  = (__half*)(S + OFF_WH);
    __half* WL  = (__half*)(S + OFF_WL);
    __half* XH  = (__half*)(S + OFF_XH);
    __half* QTH = (__half*)(S + OFF_QTH);
    __half* KH  = (__half*)(S + OFF_KH);
    __half* VH  = (__half*)(S + OFF_VH);
    __half* PH  = (__half*)(S + OFF_PH);

    // pack fp32 weights + bias
    cudaMemcpyAsync(W +      0, d_in[1],  64  * 512 * sizeof(float), cudaMemcpyDeviceToDevice);
    cudaMemcpyAsync(W +  32768, d_in[3],  64  * 512 * sizeof(float), cudaMemcpyDeviceToDevice);
    cudaMemcpyAsync(W +  65536, d_in[5],  512 * 512 * sizeof(float), cudaMemcpyDeviceToDevice);
    cudaMemcpyAsync(W + 327680, d_in[7],  64  * 512 * sizeof(float), cudaMemcpyDeviceToDevice);
    cudaMemcpyAsync(W + 360448, d_in[9],  64  * 512 * sizeof(float), cudaMemcpyDeviceToDevice);
    cudaMemcpyAsync(W + 393216, d_in[11], 64  * 512 * sizeof(float), cudaMemcpyDeviceToDevice);
    cudaMemcpyAsync(BI +   0, d_in[2],  64  * sizeof(float), cudaMemcpyDeviceToDevice);
    cudaMemcpyAsync(BI +  64, d_in[4],  64  * sizeof(float), cudaMemcpyDeviceToDevice);
    cudaMemcpyAsync(BI + 128, d_in[6],  512 * sizeof(float), cudaMemcpyDeviceToDevice);
    cudaMemcpyAsync(BI + 640, d_in[8],  64  * sizeof(float), cudaMemcpyDeviceToDevice);
    cudaMemcpyAsync(BI + 704, d_in[10], 64  * sizeof(float), cudaMemcpyDeviceToDevice);
    cudaMemcpyAsync(BI + 768, d_in[12], 64  * sizeof(float), cudaMemcpyDeviceToDevice);

    const int SM21 = STAGES * (2 * A_STG + 1 * B_STG);   // 87552
    const int SM11 = STAGES * (1 * A_STG + 1 * B_STG);   // 56832
    cudaFuncSetAttribute(gemm_mma<2, 1>, cudaFuncAttributeMaxDynamicSharedMemorySize, SM21);
    cudaFuncSetAttribute(gemm_mma<1, 1>, cudaFuncAttributeMaxDynamicSharedMemorySize, SM11);

    // fp16 conversions: W split, x single
    splitW<<<(MPAD * CH + 255) / 256, 256>>>(W, WH, WL);
    tohalf4<<<dim3(2048, BATCH), 256>>>(x, XH, 524288, (size_t)CH * HW, (size_t)CH * HW);

    // K1: projections (2-term), routed epilogue -> Y fp32, KH, VH
    gemm_mma<2, 1><<<dim3(32, 7, BATCH), 256, SM21>>>(
        WH, WL, XH, BI, Y, 512, 512, HW, HW,
        (size_t)0, (size_t)CH * HW, (size_t)MPAD * HW, 1, KH, VH,
        nullptr, nullptr);

    // q (rows 0..63 of Y) transpose -> qT fp16
    qtrans_h<<<dim3(64, BATCH), 256>>>(Y, QTH);

    // K2: energy + fused exp -> PE fp16 + row-sum partials (single-term)
    gemm_mma<1, 1><<<dim3(32, 32, BATCH), 256, SM11>>>(
        QTH, nullptr, KH, nullptr, nullptr, 64, 64, HW, 0,
        (size_t)HW * 64, (size_t)64 * HW, (size_t)0, 0,
        nullptr, nullptr, PH, PART);

    // Z reduction + fold 1/Z into v columns
    zinv_k<<<BATCH * HW / 256, 256>>>(PART, ZINV);
    vscale_k<<<dim3(4096, BATCH), 256>>>(VH, ZINV);

    // K4: pos_out = vscaled @ PE   M=512 N=4096 K=4096  (single-term fp16)
    gemm_mma<1, 1><<<dim3(32, 4, BATCH), 256, SM11>>>(
        VH, nullptr, PH, nullptr, out, HW, HW, HW, HW,
        (size_t)CH * HW, (size_t)HW * HW, (size_t)CH * HW, 0,
        nullptr, nullptr, nullptr, nullptr);

    // Channel path (fp32, Y rows 640/704/768)
    chan_energy<<<dim3(16, BATCH), 256>>>(Y + (size_t)640 * HW, Y + (size_t)704 * HW, CEP);
    reduce_ce<<<128, 256>>>(CEP, CE);
    chan_softmax<<<BATCH * 64, 64>>>(CE);
    chan_out<<<dim3(16, BATCH), 256>>>(CE, Y + (size_t)768 * HW, CO);

    // K8: d_out += co_w @ c_out + co_b   M=512 N=4096 K=64 (SIMT)
    gemm_acc<<<dim3(32, 4, BATCH), 256>>>(
        (const float*)d_in[13], CO, (const float*)d_in[14], out,
        CH, HW, CQD, CQD, HW, HW,
        (size_t)0, (size_t)CQD * HW, (size_t)CH * HW);
}

// round 8
// speedup vs baseline: 4.7063x; 1.0277x over previous
#include <cuda_runtime.h>
#include <cuda_fp16.h>
#include <cstdint>
#include <cstddef>

// ---------------------------------------------------------------------------
// Problem constants
// ---------------------------------------------------------------------------
#define BATCH 8
#define CH    512
#define CQD   64
#define HW    4096
#define MTOT  832          // packed projection rows (pq,pk,pv,cq,ck,cv)
#define MPAD  896          // padded to multiple of 128

// scratch layout (float offsets)
#define OFF_W    0u            // packed fp32 weights [832,512]
#define OFF_BI   425984u       // packed bias
#define OFF_WH   427008u       // W hi fp16 [896,512]
#define OFF_WL   656384u       // W lo fp16
#define OFF_XH   885760u       // x fp16 [8,512,4096]
#define OFF_Y    17662976u     // fp32 projections [8,896,4096] (channel rows used)
#define OFF_QTH  47023104u     // qT fp16 [8,4096,64]
#define OFF_KH   49120256u     // k fp16 [8,64,4096]
#define OFF_VH   51217408u     // v fp16 [8,512,4096] (later scaled by 1/Z)
#define OFF_PH   59606016u     // PE = exp(E-8) fp16 [8,4096,4096]
#define OFF_PART 126714880u    // row-sum partials fp32 [8,32,4096]
#define OFF_ZINV 127763456u    // 1/Z fp32 [8,4096]
#define OFF_CE   127796224u
#define OFF_CEP  127828992u
#define OFF_CO   128353280u
#define SCRATCH_FLOATS 130450432u

__device__ float g_scratch[SCRATCH_FLOATS];

// ---------------------------------------------------------------------------
// PTX helpers (base-ISA only: mma.sync / ldmatrix / cp.async)
// ---------------------------------------------------------------------------
__device__ __forceinline__ uint32_t smem_to_u32(const void* p) {
    uint32_t a;
    asm("{ .reg .u64 t; cvta.to.shared.u64 t, %1; cvt.u32.u64 %0, t; }" : "=r"(a) : "l"(p));
    return a;
}

__device__ __forceinline__ void ldsm4(uint32_t* r, uint32_t addr) {
    asm volatile("ldmatrix.sync.aligned.m8n8.x4.shared.b16 {%0,%1,%2,%3}, [%4];"
                 : "=r"(r[0]), "=r"(r[1]), "=r"(r[2]), "=r"(r[3]) : "r"(addr));
}
__device__ __forceinline__ void ldsm4t(uint32_t* r, uint32_t addr) {
    asm volatile("ldmatrix.sync.aligned.m8n8.x4.trans.shared.b16 {%0,%1,%2,%3}, [%4];"
                 : "=r"(r[0]), "=r"(r[1]), "=r"(r[2]), "=r"(r[3]) : "r"(addr));
}
__device__ __forceinline__ void mma16816(float* c, const uint32_t* a,
                                         uint32_t b0, uint32_t b1) {
    asm volatile("mma.sync.aligned.m16n8k16.row.col.f32.f16.f16.f32 "
                 "{%0,%1,%2,%3}, {%4,%5,%6,%7}, {%8,%9}, {%0,%1,%2,%3};"
                 : "+f"(c[0]), "+f"(c[1]), "+f"(c[2]), "+f"(c[3])
                 : "r"(a[0]), "r"(a[1]), "r"(a[2]), "r"(a[3]), "r"(b0), "r"(b1));
}
__device__ __forceinline__ void cp16(uint32_t dst, const void* src) {
    asm volatile("cp.async.cg.shared.global [%0], [%1], 16;" :: "r"(dst), "l"(src));
}
#define CP_COMMIT() asm volatile("cp.async.commit_group;" ::: "memory")
#define CP_WAIT1()  asm volatile("cp.async.wait_group 1;"  ::: "memory")

// ---------------------------------------------------------------------------
// fp16-split GEMM via mma.sync (HMMA), templated on term counts.
//   AT=2,BT=1: C = Ah@B + Al@B     AT=1,BT=1: C = A@B
// A: [M,K] row-major fp16. B: [K,N] row-major fp16.
// CTA tile 128x128, BK=32, 3 cp.async stages, 8 warps (4m x 2n), 2 CTAs/SM.
// Grid mapping: blockIdx.x = m-tile (fastest -> co-schedules CTAs sharing the
// same B n-block for L2 reuse), blockIdx.y = n-tile, blockIdx.z = batch.
// Epilogue modes:
//   KHo != nullptr : K1 routed projection epilogue
//       rows [0,64)    -> QTo transposed fp16 (qT [HW,64])
//       rows [64,128)  -> KHo fp16
//       rows [128,640) -> VHo fp16
//       rows [640,832) -> fp32 C (channel rows)
//   PEo != nullptr : K2 exp epilogue -> PE=fp16(exp(acc-8)) + row-sum partials
//   else           : plain fp32 C (+bias)
// ---------------------------------------------------------------------------
#define STAGES  3
#define APITCH  40                      // fp16 elems per A smem row (80B)
#define BPITCH  136                     // fp16 elems per B smem row (272B)
#define A_STG   (128 * APITCH * 2)      // 10240 B per term buffer
#define B_STG   (32 * BPITCH * 2)       // 8704 B

template<int AT, int BT>
__global__ void __launch_bounds__(256, 2) gemm_mma(
    const __half* __restrict__ Ah, const __half* __restrict__ Al,
    const __half* __restrict__ Bh,
    const float* __restrict__ bias, float* __restrict__ C,
    int K, int lda, int ldb, int ldc,
    size_t sA, size_t sB, size_t sC, int has_bias,
    __half* __restrict__ QTo, __half* __restrict__ KHo, __half* __restrict__ VHo,
    __half* __restrict__ PEo, float* __restrict__ Part)
{
    constexpr int STG_BYTES = AT * A_STG + BT * B_STG;
    extern __shared__ char smem[];
    __shared__ float sred[2][128];
    const uint32_t sb = smem_to_u32(smem);
    const int tid  = threadIdx.x;
    const int w    = tid >> 5, lane = tid & 31;
    const int wm   = w & 3,    wn   = w >> 2;
    const int b    = blockIdx.z;
    const int m0   = blockIdx.x * 128, n0 = blockIdx.y * 128;

    const __half* Ag[AT];
    Ag[0] = Ah + (size_t)b * sA + (size_t)m0 * lda;
    if (AT == 2) Ag[1] = Al + (size_t)b * sA + (size_t)m0 * lda;
    const __half* Bg0 = Bh + (size_t)b * sB + n0;

    const int nk = K >> 5;

    const int a_row = tid >> 2, a_ch = (tid & 3) << 3;     // 64 rows / iter
    const int b_row = tid >> 4, b_ch = (tid & 15) << 3;    // 16 rows / iter

    auto issue = [&](int stage, int kt) {
        const uint32_t base = sb + stage * STG_BYTES;
        const int k0 = kt << 5;
#pragma unroll
        for (int h = 0; h < AT; h++) {
            const __half* asrc = Ag[h] + k0;
            const uint32_t adst = base + h * A_STG;
#pragma unroll
            for (int r = 0; r < 2; r++) {
                int row = a_row + r * 64;
                cp16(adst + (uint32_t)(row * APITCH + a_ch) * 2,
                     asrc + (size_t)row * lda + a_ch);
            }
        }
        {
            const uint32_t bdst = base + AT * A_STG;
#pragma unroll
            for (int r = 0; r < 2; r++) {
                int row = b_row + r * 16;
                cp16(bdst + (uint32_t)(row * BPITCH + b_ch) * 2,
                     Bg0 + (size_t)(k0 + row) * ldb + b_ch);
            }
        }
    };

    float c[2][8][4];
#pragma unroll
    for (int mi = 0; mi < 2; mi++)
#pragma unroll
        for (int j = 0; j < 8; j++)
#pragma unroll
            for (int q = 0; q < 4; q++) c[mi][j][q] = 0.0f;

    issue(0, 0); CP_COMMIT();
    if (nk > 1) issue(1, 1);
    CP_COMMIT();

    const uint32_t a_lane_off = (uint32_t)((lane & 15) * APITCH + ((lane >> 4) << 3)) * 2;
    const uint32_t b_lane_off = (uint32_t)((lane & 15) * BPITCH + ((lane >> 4) << 3)) * 2;

    for (int kt = 0; kt < nk; kt++) {
        CP_WAIT1();
        __syncthreads();
        int kf = kt + STAGES - 1;
        if (kf < nk) issue(kf % STAGES, kf);
        CP_COMMIT();

        const int stage = kt % STAGES;
        const uint32_t ab = sb + stage * STG_BYTES;
        const uint32_t bb = ab + AT * A_STG;

#pragma unroll
        for (int ks = 0; ks < 2; ks++) {
            uint32_t afr[AT][2][4];
            uint32_t bfr[4][4];
#pragma unroll
            for (int h = 0; h < AT; h++)
#pragma unroll
                for (int mi = 0; mi < 2; mi++)
                    ldsm4(afr[h][mi],
                          ab + h * A_STG + a_lane_off +
                          (uint32_t)((wm * 32 + mi * 16) * APITCH + ks * 16) * 2);
#pragma unroll
            for (int nj = 0; nj < 4; nj++)
                ldsm4t(bfr[nj],
                       bb + b_lane_off +
                       (uint32_t)(ks * 16 * BPITCH + wn * 64 + nj * 16) * 2);
#pragma unroll
            for (int mi = 0; mi < 2; mi++)
#pragma unroll
                for (int j = 0; j < 8; j++) {
                    const int nj = j >> 1, hf = (j & 1) << 1;
                    mma16816(c[mi][j], afr[0][mi], bfr[nj][hf], bfr[nj][hf + 1]);
                    if (AT == 2)
                        mma16816(c[mi][j], afr[1][mi], bfr[nj][hf], bfr[nj][hf + 1]);
                }
        }
        __syncthreads();
    }

    // ---- epilogue ----
    const int colbase = n0 + wn * 64 + (lane & 3) * 2;
    if (KHo != nullptr) {
        // routed projection epilogue (K1)
#pragma unroll
        for (int mi = 0; mi < 2; mi++)
#pragma unroll
            for (int rr = 0; rr < 2; rr++) {
                const int row = m0 + wm * 32 + mi * 16 + (lane >> 2) + rr * 8;
                if (row >= MTOT) continue;
                const float bv = bias[row];
                if (row < 64) {
                    // qT transposed write: QTo[(b*HW + col)*64 + row]
                    __half* qb = QTo + (size_t)b * HW * 64 + row;
#pragma unroll
                    for (int j = 0; j < 8; j++) {
                        const int col = colbase + j * 8;
                        qb[(size_t)col * 64]       =
                            __float2half_rn(c[mi][j][rr * 2] + bv);
                        qb[(size_t)(col + 1) * 64] =
                            __float2half_rn(c[mi][j][rr * 2 + 1] + bv);
                    }
                } else if (row < 128) {
                    __half* ph = KHo + ((size_t)b * 64 + (row - 64)) * HW + colbase;
#pragma unroll
                    for (int j = 0; j < 8; j++)
                        *reinterpret_cast<__half2*>(ph + j * 8) = __halves2half2(
                            __float2half_rn(c[mi][j][rr * 2] + bv),
                            __float2half_rn(c[mi][j][rr * 2 + 1] + bv));
                } else if (row < 640) {
                    __half* ph = VHo + ((size_t)b * 512 + (row - 128)) * HW + colbase;
#pragma unroll
                    for (int j = 0; j < 8; j++)
                        *reinterpret_cast<__half2*>(ph + j * 8) = __halves2half2(
                            __float2half_rn(c[mi][j][rr * 2] + bv),
                            __float2half_rn(c[mi][j][rr * 2 + 1] + bv));
                } else {
                    float* p = C + (size_t)b * sC + (size_t)row * ldc + colbase;
#pragma unroll
                    for (int j = 0; j < 8; j++)
                        *reinterpret_cast<float2*>(p + j * 8) =
                            make_float2(c[mi][j][rr * 2] + bv, c[mi][j][rr * 2 + 1] + bv);
                }
            }
    } else if (PEo != nullptr) {
        // K2 exp epilogue: PE = fp16(exp(acc - 8)), plus row-sum partials.
#pragma unroll
        for (int mi = 0; mi < 2; mi++)
#pragma unroll
            for (int rr = 0; rr < 2; rr++) {
                const int rloc = wm * 32 + mi * 16 + (lane >> 2) + rr * 8;
                __half* pp = PEo + ((size_t)b * HW + m0 + rloc) * HW + colbase;
                float rsum = 0.0f;
#pragma unroll
                for (int j = 0; j < 8; j++) {
                    float e0 = __expf(c[mi][j][rr * 2]     - 8.0f);
                    float e1 = __expf(c[mi][j][rr * 2 + 1] - 8.0f);
                    __half h0 = __float2half_rn(e0), h1 = __float2half_rn(e1);
                    *reinterpret_cast<__half2*>(pp + j * 8) = __halves2half2(h0, h1);
                    rsum += __half2float(h0) + __half2float(h1);
                }
                rsum += __shfl_xor_sync(0xffffffffu, rsum, 1);
                rsum += __shfl_xor_sync(0xffffffffu, rsum, 2);
                if ((lane & 3) == 0) sred[wn][rloc] = rsum;
            }
        __syncthreads();
        if (tid < 128) {
            float z = sred[0][tid] + sred[1][tid];
            Part[((size_t)b * 32 + blockIdx.y) * HW + m0 + tid] = z;
        }
    } else {
#pragma unroll
        for (int mi = 0; mi < 2; mi++) {
            const int r0 = m0 + wm * 32 + mi * 16 + (lane >> 2);
            const float bv0 = has_bias ? bias[r0]     : 0.0f;
            const float bv1 = has_bias ? bias[r0 + 8] : 0.0f;
            float* p0 = C + (size_t)b * sC + (size_t)r0 * ldc + colbase;
            float* p1 = p0 + (size_t)8 * ldc;
#pragma unroll
            for (int j = 0; j < 8; j++) {
                *reinterpret_cast<float2*>(p0 + j * 8) =
                    make_float2(c[mi][j][0] + bv0, c[mi][j][1] + bv0);
                *reinterpret_cast<float2*>(p1 + j * 8) =
                    make_float2(c[mi][j][2] + bv1, c[mi][j][3] + bv1);
            }
        }
    }
}

// ---------------------------------------------------------------------------
// Z reduction + v column scaling
// ---------------------------------------------------------------------------
__global__ void zinv_k(const float* __restrict__ Part, float* __restrict__ zinv)
{
    int i = blockIdx.x * 256 + threadIdx.x;   // over B*HW
    int b = i >> 12, r = i & 4095;
    float s = 0.0f;
#pragma unroll
    for (int jt = 0; jt < 32; jt++) s += Part[((size_t)b * 32 + jt) * HW + r];
    zinv[i] = 1.0f / s;
}

__global__ void vscale_k(__half* __restrict__ VH, const float* __restrict__ zinv)
{
    const int b = blockIdx.y;
    int idx = blockIdx.x * 256 + threadIdx.x;   // over 512*2048 half2 per batch
    int c  = idx >> 11;
    int i2 = idx & 2047;
    __half2* p = reinterpret_cast<__half2*>(VH + ((size_t)b * 512 + c) * HW) + i2;
    float2 f = __half22float2(*p);
    float z0 = zinv[(size_t)b * HW + 2 * i2];
    float z1 = zinv[(size_t)b * HW + 2 * i2 + 1];
    *p = __floats2half2_rn(f.x * z0, f.y * z1);
}

// ---------------------------------------------------------------------------
// fp16 conversions
// ---------------------------------------------------------------------------
__global__ void tohalf4(const float* __restrict__ in, __half* __restrict__ hi,
                        int count4, size_t in_bs, size_t out_bs)
{
    size_t b = blockIdx.y;
    int i = blockIdx.x * 256 + threadIdx.x;
    if (i >= count4) return;
    float4 v = reinterpret_cast<const float4*>(in + b * in_bs)[i];
    __half2* ph = reinterpret_cast<__half2*>(hi + b * out_bs);
    ph[2 * i]     = __floats2half2_rn(v.x, v.y);
    ph[2 * i + 1] = __floats2half2_rn(v.z, v.w);
}

__global__ void splitW(const float* __restrict__ in, __half* __restrict__ hi,
                       __half* __restrict__ lo)
{
    int i = blockIdx.x * 256 + threadIdx.x;     // 0..896*512-1
    float v = (i < MTOT * CH) ? in[i] : 0.0f;
    __half h = __float2half_rn(v);
    hi[i] = h;
    lo[i] = __float2half_rn(v - __half2float(h));
}

// ---------------------------------------------------------------------------
// SIMT f32x2 GEMM (small K8 accumulate)
// ---------------------------------------------------------------------------
__device__ __forceinline__ unsigned long long pk2(float lo, float hi) {
    unsigned long long r;
    asm("mov.b64 %0, {%1, %2};" : "=l"(r) : "f"(lo), "f"(hi));
    return r;
}
__device__ __forceinline__ unsigned long long fma2(unsigned long long a,
                                                   unsigned long long b,
                                                   unsigned long long c) {
    unsigned long long d;
    asm("fma.rn.f32x2 %0, %1, %2, %3;" : "=l"(d) : "l"(a), "l"(b), "l"(c));
    return d;
}
__device__ __forceinline__ float2 u2f(unsigned long long u) {
    float2 f;
    asm("mov.b64 {%0, %1}, %2;" : "=f"(f.x), "=f"(f.y) : "l"(u));
    return f;
}

__global__ __launch_bounds__(256, 2)
void gemm_acc(const float* __restrict__ A, const float* __restrict__ Bm,
              const float* __restrict__ bias, float* __restrict__ Cm,
              int M, int N, int K, int lda, int ldb, int ldc,
              size_t sA, size_t sB, size_t sC)
{
    __shared__ float As[16][128 + 4];
    __shared__ float Bs[16][128];

    const int b  = blockIdx.z;
    const float* Ab = A + (size_t)b * sA;
    const float* Bb = Bm + (size_t)b * sB;
    float*       Cb = Cm + (size_t)b * sC;

    const int m0 = blockIdx.y * 128;
    const int n0 = blockIdx.x * 128;
    const int t  = threadIdx.x;
    const int tm0 = (t >> 4) << 3;
    const int tn0 = (t & 15) << 3;

    unsigned long long acc[8][4];
#pragma unroll
    for (int i = 0; i < 8; i++)
#pragma unroll
        for (int j = 0; j < 4; j++) acc[i][j] = 0ull;

    for (int k0 = 0; k0 < K; k0 += 16) {
#pragma unroll
        for (int r = 0; r < 2; r++) {
            int idx = t + r * 256;
            int row = idx >> 2;
            int c4  = (idx & 3) << 2;
            float4 v = make_float4(0.f, 0.f, 0.f, 0.f);
            if (m0 + row < M)
                v = *reinterpret_cast<const float4*>(Ab + (size_t)(m0 + row) * lda + k0 + c4);
            As[c4 + 0][row] = v.x; As[c4 + 1][row] = v.y;
            As[c4 + 2][row] = v.z; As[c4 + 3][row] = v.w;
        }
#pragma unroll
        for (int r = 0; r < 2; r++) {
            int idx = t + r * 256;
            int kr  = idx >> 5;
            int n4  = (idx & 31) << 2;
            float4 v = *reinterpret_cast<const float4*>(Bb + (size_t)(k0 + kr) * ldb + n0 + n4);
            *reinterpret_cast<float4*>(&Bs[kr][n4]) = v;
        }
        __syncthreads();
#pragma unroll
        for (int kk = 0; kk < 16; kk++) {
            float4 a0 = *reinterpret_cast<const float4*>(&As[kk][tm0]);
            float4 a1 = *reinterpret_cast<const float4*>(&As[kk][tm0 + 4]);
            ulonglong2 bl0 = *reinterpret_cast<const ulonglong2*>(&Bs[kk][tn0]);
            ulonglong2 bl1 = *reinterpret_cast<const ulonglong2*>(&Bs[kk][tn0 + 4]);
            unsigned long long bv[4] = {bl0.x, bl0.y, bl1.x, bl1.y};
            float av[8] = {a0.x, a0.y, a0.z, a0.w, a1.x, a1.y, a1.z, a1.w};
#pragma unroll
            for (int i = 0; i < 8; i++) {
                unsigned long long a2 = pk2(av[i], av[i]);
#pragma unroll
                for (int j = 0; j < 4; j++) acc[i][j] = fma2(a2, bv[j], acc[i][j]);
            }
        }
        __syncthreads();
    }
#pragma unroll
    for (int i = 0; i < 8; i++) {
        int m = m0 + tm0 + i;
        if (m >= M) continue;
        float bsv = bias[m];
        float* crow = Cb + (size_t)m * ldc + n0 + tn0;
#pragma unroll
        for (int j = 0; j < 4; j++) {
            float2 f = u2f(acc[i][j]);
            float2 o = *reinterpret_cast<const float2*>(crow + j * 2);
            f.x += bsv + o.x; f.y += bsv + o.y;
            *reinterpret_cast<float2*>(crow + j * 2) = f;
        }
    }
}

// ---------------------------------------------------------------------------
// Channel attention kernels (fp32, small)
// ---------------------------------------------------------------------------
__global__ void chan_energy(const float* __restrict__ cq, const float* __restrict__ ck,
                            float* __restrict__ part)
{
    __shared__ float sq[64][65];
    __shared__ float sk[64][65];
    const int b = blockIdx.y;
    const int split = blockIdx.x;
    const float* cqb = cq + (size_t)b * MPAD * HW;
    const float* ckb = ck + (size_t)b * MPAD * HW;
    const int t = threadIdx.x;
    const int p0 = (t >> 4) * 4;
    const int q0 = (t & 15) * 4;

    float acc[4][4];
#pragma unroll
    for (int i = 0; i < 4; i++)
#pragma unroll
        for (int j = 0; j < 4; j++) acc[i][j] = 0.f;

    for (int c = 0; c < 4; c++) {
        const int nb = (split * 4 + c) * 64;
        __syncthreads();
#pragma unroll
        for (int i = 0; i < 16; i++) {
            int idx = t + i * 256;
            int row = idx >> 6, col = idx & 63;
            sq[row][col] = cqb[(size_t)row * HW + nb + col];
            sk[row][col] = ckb[(size_t)row * HW + nb + col];
        }
        __syncthreads();
        for (int nn = 0; nn < 64; nn++) {
            float aq[4], bk[4];
#pragma unroll
            for (int i = 0; i < 4; i++) aq[i] = sq[p0 + i][nn];
#pragma unroll
            for (int j = 0; j < 4; j++) bk[j] = sk[q0 + j][nn];
#pragma unroll
            for (int i = 0; i < 4; i++)
#pragma unroll
                for (int j = 0; j < 4; j++) acc[i][j] += aq[i] * bk[j];
        }
    }
    float* out = part + (size_t)split * (BATCH * 4096) + (size_t)b * 4096;
#pragma unroll
    for (int i = 0; i < 4; i++)
#pragma unroll
        for (int j = 0; j < 4; j++)
            out[(p0 + i) * 64 + (q0 + j)] = acc[i][j];
}

__global__ void reduce_ce(const float* __restrict__ part, float* __restrict__ cE)
{
    int i = blockIdx.x * 256 + threadIdx.x;
    float s = 0.f;
#pragma unroll
    for (int k = 0; k < 16; k++) s += part[(size_t)k * (BATCH * 4096) + i];
    cE[i] = s;
}

__global__ void chan_softmax(float* __restrict__ cE)
{
    __shared__ float red[64];
    const int row = blockIdx.x;
    float* rp = cE + (size_t)row * 64;
    const int t = threadIdx.x;
    float v = rp[t];
    red[t] = v; __syncthreads();
    for (int s = 32; s > 0; s >>= 1) {
        if (t < s) red[t] = fmaxf(red[t], red[t + s]);
        __syncthreads();
    }
    float m = red[0]; __syncthreads();
    float e = __expf(v - m);
    red[t] = e; __syncthreads();
    for (int s = 32; s > 0; s >>= 1) {
        if (t < s) red[t] += red[t + s];
        __syncthreads();
    }
    rp[t] = e / red[0];
}

__global__ void chan_out(const float* __restrict__ cattn, const float* __restrict__ cv,
                         float* __restrict__ cout)
{
    __shared__ float sa[4096];
    const int b = blockIdx.y;
    const int n = blockIdx.x * 256 + threadIdx.x;
    const float* at = cattn + (size_t)b * 4096;
    for (int i = threadIdx.x; i < 4096; i += 256) sa[i] = at[i];
    __syncthreads();

    const float* cvb = cv + (size_t)b * MPAD * HW;
    float acc[64];
#pragma unroll
    for (int p = 0; p < 64; p++) acc[p] = 0.f;
    for (int q = 0; q < 64; q++) {
        float vv = cvb[(size_t)q * HW + n];
#pragma unroll
        for (int p = 0; p < 64; p++) acc[p] += sa[p * 64 + q] * vv;
    }
    float* ob = cout + (size_t)b * CQD * HW;
#pragma unroll
    for (int p = 0; p < 64; p++) ob[(size_t)p * HW + n] = acc[p];
}

// ---------------------------------------------------------------------------
// Launch
// ---------------------------------------------------------------------------
extern "C" void kernel_launch(void* const* d_in, const int* in_sizes, int n_in,
                              void* d_out, int out_size)
{
    (void)in_sizes; (void)n_in; (void)out_size;

    const float* x = (const float*)d_in[0];

    float* S = nullptr;
    cudaGetSymbolAddress((void**)&S, g_scratch);

    float* W    = S + OFF_W;
    float* BI   = S + OFF_BI;
    float* Y    = S + OFF_Y;
    float* PART = S + OFF_PART;
    float* ZINV = S + OFF_ZINV;
    float* CE   = S + OFF_CE;
    float* CEP  = S + OFF_CEP;
    float* CO   = S + OFF_CO;
    float* out  = (float*)d_out;

    __half* WH  = (__half*)(S + OFF_WH);
    __half* WL  = (__half*)(S + OFF_WL);
    __half* XH  = (__half*)(S + OFF_XH);
    __half* QTH = (__half*)(S + OFF_QTH);
    __half* KH  = (__half*)(S + OFF_KH);
    __half* VH  = (__half*)(S + OFF_VH);
    __half* PH  = (__half*)(S + OFF_PH);

    // pack fp32 weights + bias
    cudaMemcpyAsync(W +      0, d_in[1],  64  * 512 * sizeof(float), cudaMemcpyDeviceToDevice);
    cudaMemcpyAsync(W +  32768, d_in[3],  64  * 512 * sizeof(float), cudaMemcpyDeviceToDevice);
    cudaMemcpyAsync(W +  65536, d_in[5],  512 * 512 * sizeof(float), cudaMemcpyDeviceToDevice);
    cudaMemcpyAsync(W + 327680, d_in[7],  64  * 512 * sizeof(float), cudaMemcpyDeviceToDevice);
    cudaMemcpyAsync(W + 360448, d_in[9],  64  * 512 * sizeof(float), cudaMemcpyDeviceToDevice);
    cudaMemcpyAsync(W + 393216, d_in[11], 64  * 512 * sizeof(float), cudaMemcpyDeviceToDevice);
    cudaMemcpyAsync(BI +   0, d_in[2],  64  * sizeof(float), cudaMemcpyDeviceToDevice);
    cudaMemcpyAsync(BI +  64, d_in[4],  64  * sizeof(float), cudaMemcpyDeviceToDevice);
    cudaMemcpyAsync(BI + 128, d_in[6],  512 * sizeof(float), cudaMemcpyDeviceToDevice);
    cudaMemcpyAsync(BI + 640, d_in[8],  64  * sizeof(float), cudaMemcpyDeviceToDevice);
    cudaMemcpyAsync(BI + 704, d_in[10], 64  * sizeof(float), cudaMemcpyDeviceToDevice);
    cudaMemcpyAsync(BI + 768, d_in[12], 64  * sizeof(float), cudaMemcpyDeviceToDevice);

    const int SM21 = STAGES * (2 * A_STG + 1 * B_STG);   // 87552
    const int SM11 = STAGES * (1 * A_STG + 1 * B_STG);   // 56832
    cudaFuncSetAttribute(gemm_mma<2, 1>, cudaFuncAttributeMaxDynamicSharedMemorySize, SM21);
    cudaFuncSetAttribute(gemm_mma<1, 1>, cudaFuncAttributeMaxDynamicSharedMemorySize, SM11);

    // fp16 conversions: W split, x single
    splitW<<<(MPAD * CH + 255) / 256, 256>>>(W, WH, WL);
    tohalf4<<<dim3(2048, BATCH), 256>>>(x, XH, 524288, (size_t)CH * HW, (size_t)CH * HW);

    // K1: projections (2-term), routed epilogue -> QTH (transposed), KH, VH,
    //     channel rows fp32 Y.  Grid: x=m (fastest, shares B per n-block).
    gemm_mma<2, 1><<<dim3(7, 32, BATCH), 256, SM21>>>(
        WH, WL, XH, BI, Y, 512, 512, HW, HW,
        (size_t)0, (size_t)CH * HW, (size_t)MPAD * HW, 1, QTH, KH, VH,
        nullptr, nullptr);

    // K2: energy + fused exp -> PE fp16 + row-sum partials (single-term)
    gemm_mma<1, 1><<<dim3(32, 32, BATCH), 256, SM11>>>(
        QTH, nullptr, KH, nullptr, nullptr, 64, 64, HW, 0,
        (size_t)HW * 64, (size_t)64 * HW, (size_t)0, 0,
        nullptr, nullptr, nullptr, PH, PART);

    // Z reduction + fold 1/Z into v columns
    zinv_k<<<BATCH * HW / 256, 256>>>(PART, ZINV);
    vscale_k<<<dim3(4096, BATCH), 256>>>(VH, ZINV);

    // K4: pos_out = vscaled @ PE   M=512 N=4096 K=4096  (single-term fp16)
    gemm_mma<1, 1><<<dim3(4, 32, BATCH), 256, SM11>>>(
        VH, nullptr, PH, nullptr, out, HW, HW, HW, HW,
        (size_t)CH * HW, (size_t)HW * HW, (size_t)CH * HW, 0,
        nullptr, nullptr, nullptr, nullptr, nullptr);

    // Channel path (fp32, Y rows 640/704/768)
    chan_energy<<<dim3(16, BATCH), 256>>>(Y + (size_t)640 * HW, Y + (size_t)704 * HW, CEP);
    reduce_ce<<<128, 256>>>(CEP, CE);
    chan_softmax<<<BATCH * 64, 64>>>(CE);
    chan_out<<<dim3(16, BATCH), 256>>>(CE, Y + (size_t)768 * HW, CO);

    // K8: d_out += co_w @ c_out + co_b   M=512 N=4096 K=64 (SIMT)
    gemm_acc<<<dim3(32, 4, BATCH), 256>>>(
        (const float*)d_in[13], CO, (const float*)d_in[14], out,
        CH, HW, CQD, CQD, HW, HW,
        (size_t)0, (size_t)CQD * HW, (size_t)CH * HW);
}